// round 4
// baseline (speedup 1.0000x reference)
#include <cuda_runtime.h>
#include <cuda_bf16.h>
#include <cstdint>

// ---------------------------------------------------------------------------
// EarthAttention3D: B=2, nW=840, N=144, C=192, H=6, d=32
//   GEMMs on tcgen05 kind::tf32 when compiled arch-specific (sm_103a);
//   SIMT fp32 fallback body for plain compute_103 passes (tcgen05 is 'a'-only).
// ---------------------------------------------------------------------------

typedef unsigned long long ull;
typedef unsigned int u32;

#if defined(__CUDA_ARCH_FEAT_SM103_ALL) || defined(__CUDA_ARCH_FEAT_SM100_ALL) || \
    defined(__CUDA_ARCH_SPECIFIC__)
#define TC_OK 1
#else
#define TC_OK 0
#endif

#define NW     840
#define NTOK   144
#define DIM    192
#define HEADS  6
#define HDIM   32
#define BATCH  2
#define MTOT   (BATCH*NW*NTOK)          // 241920
#define MTILES (MTOT/128)               // 1890
#define TABLE  3312
#define QSCALE 0.17677669529663687f     // 32^-0.5

__device__ float g_qkv[(size_t)MTOT * 576];   // 557 MB scratch
__device__ float g_att[(size_t)MTOT * DIM];   // 186 MB scratch

// ---------------- generic helpers (valid on all targets) ----------------
__device__ __forceinline__ ull pk(float x, float y) {
    ull r; asm("mov.b64 %0,{%1,%2};" : "=l"(r) : "f"(x), "f"(y)); return r;
}
__device__ __forceinline__ float2 upk(ull a) {
    float2 f; asm("mov.b64 {%0,%1},%2;" : "=f"(f.x), "=f"(f.y) : "l"(a)); return f;
}
__device__ __forceinline__ void fma2(ull& d, ull a, ull b) {
    asm("fma.rn.f32x2 %0,%1,%2,%0;" : "+l"(d) : "l"(a), "l"(b));
}
__device__ __forceinline__ u32 smem_u32(const void* p) {
    u32 r; asm("{ .reg .u64 t; cvta.to.shared.u64 t, %1; cvt.u32.u64 %0, t; }"
               : "=r"(r) : "l"(p)); return r;
}

#if TC_OK
// ---------------- tcgen05 helpers (arch-specific targets only) -----------
__device__ __forceinline__ u32 cvt_tf32(float f) {
    u32 r; asm("cvt.rn.tf32.f32 %0, %1;" : "=r"(r) : "f"(f)); return r;
}
__device__ __forceinline__ void mbar_init(u32 mb, u32 cnt) {
    asm volatile("mbarrier.init.shared.b64 [%0], %1;" :: "r"(mb), "r"(cnt) : "memory");
}
__device__ __forceinline__ void mbar_wait(u32 mb, u32 par) {
    asm volatile(
        "{\n\t.reg .pred P;\n\t"
        "W%=:\n\t"
        "mbarrier.try_wait.parity.acquire.cta.shared::cta.b64 P, [%0], %1, 0x989680;\n\t"
        "@P bra D%=;\n\t"
        "bra W%=;\n\t"
        "D%=:\n\t}"
        :: "r"(mb), "r"(par) : "memory");
}
__device__ __forceinline__ ull mk_desc(u32 addr) {   // SW128 K-major, Blackwell v1
    return ((ull)2 << 61) | ((ull)1 << 46) | ((ull)64 << 32) | ((ull)1 << 16)
         | ((addr >> 4) & 0x3FFFull);
}

#define LDTM32(r, ta) \
    asm volatile( \
        "tcgen05.ld.sync.aligned.32x32b.x32.b32 " \
        "{%0, %1, %2, %3, %4, %5, %6, %7, " \
        " %8, %9, %10, %11, %12, %13, %14, %15, " \
        " %16, %17, %18, %19, %20, %21, %22, %23, " \
        " %24, %25, %26, %27, %28, %29, %30, %31}, [%32];" \
        : "=r"((r)[0]),  "=r"((r)[1]),  "=r"((r)[2]),  "=r"((r)[3]), \
          "=r"((r)[4]),  "=r"((r)[5]),  "=r"((r)[6]),  "=r"((r)[7]), \
          "=r"((r)[8]),  "=r"((r)[9]),  "=r"((r)[10]), "=r"((r)[11]), \
          "=r"((r)[12]), "=r"((r)[13]), "=r"((r)[14]), "=r"((r)[15]), \
          "=r"((r)[16]), "=r"((r)[17]), "=r"((r)[18]), "=r"((r)[19]), \
          "=r"((r)[20]), "=r"((r)[21]), "=r"((r)[22]), "=r"((r)[23]), \
          "=r"((r)[24]), "=r"((r)[25]), "=r"((r)[26]), "=r"((r)[27]), \
          "=r"((r)[28]), "=r"((r)[29]), "=r"((r)[30]), "=r"((r)[31]) \
        : "r"(ta))

// idesc: dtype=F32(1)<<4, atype=TF32(2)<<7, btype=TF32(2)<<10, N/8<<17, M/16<<24
static constexpr u32 IDESC_TF32 =
    (1u << 4) | (2u << 7) | (2u << 10) | ((64u / 8) << 17) | ((128u / 16) << 24);

__device__ __forceinline__ void mma_tf32(u32 dt, ull ad, ull bd, u32 en) {
    asm volatile(
        "{\n\t.reg .pred p;\n\t"
        "setp.ne.u32 p, %4, 0;\n\t"
        "tcgen05.mma.cta_group::1.kind::tf32 [%0], %1, %2, %3, {%5,%5,%5,%5}, p;\n\t}"
        :: "r"(dt), "l"(ad), "l"(bd), "r"(IDESC_TF32), "r"(en), "r"(0u) : "memory");
}
#endif  // TC_OK

// ---------------------------------------------------------------------------
// GEMM (NT): C[m,n] = A[m,:192] . W[n,:192] + bias[n]
// CTA: 128-row M tile, loops Ntot/64 N-subtiles. 256 threads.
// SMEM (from 1024-aligned base0):
//   +0 tmemptr | +16 mbar[2] | +1024 A(96KB, SW128 slabs of 128x32f)
//   +99328 W0(48KB) | +148480 W1(48KB)
// ---------------------------------------------------------------------------
#define G_OFF_A   1024u
#define G_OFF_W0  99328u
#define G_OFF_W1  148480u
#define G_SMEM_SZ (197632 + 1024)

#if TC_OK
__device__ __forceinline__ void gtc_loadW(const float* __restrict__ Wsrc,
                                          char* dst, int tid0, int nthr) {
    for (int idx = tid0; idx < 3072; idx += nthr) {
        int row = idx / 48, c4 = idx - row * 48;
        float4 v = *(const float4*)(Wsrc + row * 192 + c4 * 4);
        uint4 t;
        t.x = cvt_tf32(v.x); t.y = cvt_tf32(v.y);
        t.z = cvt_tf32(v.z); t.w = cvt_tf32(v.w);
        u32 bo = (u32)(row * 128 + (c4 & 7) * 16);
        bo ^= (bo >> 3) & 0x70;
        *(uint4*)(dst + (c4 >> 3) * 8192 + bo) = t;
    }
}

__device__ __forceinline__ void gtc_epilogue(u32 tmem, int bufsel, int nsub,
        float* __restrict__ C, const float* __restrict__ bias, int Ntot,
        int bm, int wid, int lane) {
    u32 dt = tmem + bufsel * 64;
    u32 dr[64];
    asm volatile("tcgen05.fence::after_thread_sync;" ::: "memory");
    LDTM32(dr, dt);
    LDTM32(dr + 32, dt + 32);
    asm volatile("tcgen05.wait::ld.sync.aligned;" ::: "memory");
    asm volatile("tcgen05.fence::before_thread_sync;" ::: "memory");
    int m = bm + wid * 32 + lane;
    float* crow = C + (size_t)m * Ntot + nsub * 64;
    const float4* b4 = (const float4*)(bias + nsub * 64);
#pragma unroll
    for (int c = 0; c < 16; c++) {
        float4 bb = b4[c];
        float4 o;
        o.x = __uint_as_float(dr[4 * c + 0]) + bb.x;
        o.y = __uint_as_float(dr[4 * c + 1]) + bb.y;
        o.z = __uint_as_float(dr[4 * c + 2]) + bb.z;
        o.w = __uint_as_float(dr[4 * c + 3]) + bb.w;
        *(float4*)(crow + 4 * c) = o;
    }
}
#endif  // TC_OK

__global__ __launch_bounds__(256, 1) void gemm_tc(
    const float* __restrict__ A, const float* __restrict__ W,
    const float* __restrict__ bias, float* __restrict__ C, int Ntot)
{
    extern __shared__ char gsm_raw[];
    u32 sb_raw = smem_u32(gsm_raw);
    u32 sb0 = (sb_raw + 1023u) & ~1023u;
    char* gp = gsm_raw + (sb0 - sb_raw);

    const int tid = threadIdx.x;
    const int bm = blockIdx.x * 128;

#if TC_OK
    const int wid = tid >> 5, lane = tid & 31;
    const int niter = Ntot >> 6;

    if (wid == 0) {
        asm volatile("tcgen05.alloc.cta_group::1.sync.aligned.shared::cta.b32 [%0], %1;"
                     :: "r"(sb0), "r"(128u) : "memory");
        asm volatile("tcgen05.relinquish_alloc_permit.cta_group::1.sync.aligned;");
    }
    if (tid == 0) { mbar_init(sb0 + 16, 1); mbar_init(sb0 + 24, 1); }
    __syncthreads();
    u32 tmem;
    asm("ld.shared.b32 %0, [%1];" : "=r"(tmem) : "r"(sb0));

    // ---- load A tile (128 x 192), tf32-round, SW128 slabs ----
    const float* Ab = A + (size_t)bm * 192;
    for (int idx = tid; idx < 6144; idx += 256) {
        int row = idx / 48, c4 = idx - row * 48;
        float4 v = *(const float4*)(Ab + row * 192 + c4 * 4);
        uint4 t;
        t.x = cvt_tf32(v.x); t.y = cvt_tf32(v.y);
        t.z = cvt_tf32(v.z); t.w = cvt_tf32(v.w);
        u32 bo = (u32)(row * 128 + (c4 & 7) * 16);
        bo ^= (bo >> 3) & 0x70;
        *(uint4*)(gp + G_OFF_A + (c4 >> 3) * 16384 + bo) = t;
    }
    // ---- load W subtile 0 ----
    gtc_loadW(W, gp + G_OFF_W0, tid, 256);
    asm volatile("fence.proxy.async.shared::cta;" ::: "memory");
    __syncthreads();

    const ull descA = mk_desc(sb0 + G_OFF_A);
    u32 ph[2] = {0, 0};

    for (int it = 0; it < niter; it++) {
        const int buf = it & 1;
        if (tid == 0) {
            ull descW = mk_desc(sb0 + (buf ? G_OFF_W1 : G_OFF_W0));
            u32 dtm = tmem + buf * 64;
#pragma unroll
            for (int k = 0; k < 24; k++)
                mma_tf32(dtm, descA + (k >> 2) * 1024 + (k & 3) * 2,
                              descW + (k >> 2) * 512 + (k & 3) * 2, (u32)(k > 0));
            asm volatile(
                "tcgen05.commit.cta_group::1.mbarrier::arrive::one.shared::cluster.b64 [%0];"
                :: "r"(sb0 + 16 + buf * 8) : "memory");
        }
        if (it == 0) {
            if (niter > 1)
                gtc_loadW(W + (size_t)64 * 192, gp + G_OFF_W1, tid, 256);
        } else {
            const int pb = buf ^ 1;
            mbar_wait(sb0 + 16 + pb * 8, ph[pb]);
            ph[pb] ^= 1;
            if (tid < 128) {
                gtc_epilogue(tmem, pb, it - 1, C, bias, Ntot, bm, wid, lane);
            } else if (it + 1 < niter) {
                gtc_loadW(W + (size_t)(it + 1) * 64 * 192,
                          gp + (pb ? G_OFF_W1 : G_OFF_W0), tid - 128, 128);
            }
        }
        asm volatile("fence.proxy.async.shared::cta;" ::: "memory");
        __syncthreads();
    }
    // final epilogue
    {
        const int lb = (niter - 1) & 1;
        mbar_wait(sb0 + 16 + lb * 8, ph[lb]);
        if (tid < 128)
            gtc_epilogue(tmem, lb, niter - 1, C, bias, Ntot, bm, wid, lane);
    }
    __syncthreads();
    if (wid == 0)
        asm volatile("tcgen05.dealloc.cta_group::1.sync.aligned.b32 %0, %1;"
                     :: "r"(tmem), "r"(128u));

#else  // --------- SIMT fp32 fallback (plain compute_103 pass) ----------
    float* As = (float*)gp;
    const float* Ab = A + (size_t)bm * 192;
    for (int i = tid; i < 128 * 48; i += 256)
        ((float4*)As)[i] = ((const float4*)Ab)[i];
    __syncthreads();
    for (int idx = tid; idx < 128 * Ntot; idx += 256) {
        int col = idx >> 7, row = idx & 127;
        const float4* ar = (const float4*)(As + row * 192);
        const float4* wr = (const float4*)(W + (size_t)col * 192);
        float s = 0.f;
#pragma unroll 8
        for (int k = 0; k < 48; k++) {
            float4 a = ar[k], w = wr[k];
            s += a.x * w.x + a.y * w.y + a.z * w.z + a.w * w.w;
        }
        C[(size_t)(bm + row) * Ntot + col] = s + bias[col];
    }
#endif
}

// ---------------------------------------------------------------------------
// Attention per (b, w, h). 576 threads, full-S in SMEM. (unchanged)
// ---------------------------------------------------------------------------
#define OFS_QT 20736
#define OFS_KT (OFS_QT + 32*146)
#define OFS_V  (OFS_KT + 32*146)
#define OFS_BC (OFS_V + 144*33)
#define ATTN_SMEM ((OFS_BC + TABLE) * 4)

__global__ __launch_bounds__(576, 1) void attn_kernel(
    const float* __restrict__ qkv, const float* __restrict__ bias_table,
    const int* __restrict__ pidx, const float* __restrict__ mask,
    float* __restrict__ outp)
{
    extern __shared__ __align__(16) float sm[];
    float* S    = sm;
    float* qT   = sm + OFS_QT;
    float* kT   = sm + OFS_KT;
    float* Vv   = sm + OFS_V;
    float* bcol = sm + OFS_BC;

    const int tid = threadIdx.x;
    const int bx  = blockIdx.x;
    const int w = bx / 12;
    const int rr = bx - w * 12;
    const int b = rr / 6;
    const int h = rr - b * 6;

    const size_t base = (size_t)(b * NW + w) * NTOK * 576 + h * HDIM;
    const float* qg = qkv + base;
    const float* kg = qg + 192;
    const float* vg = qg + 384;

    for (int idx = tid; idx < NTOK * HDIM; idx += 576) {
        int n = idx >> 5, dd = idx & 31;
        qT[dd * 146 + n] = qg[(size_t)n * 576 + dd] * QSCALE;
        kT[dd * 146 + n] = kg[(size_t)n * 576 + dd];
        Vv[n * 33 + dd]  = vg[(size_t)n * 576 + dd];
    }
    for (int i = tid; i < TABLE; i += 576)
        bcol[i] = bias_table[(size_t)i * (NW * HEADS) + w * HEADS + h];
    __syncthreads();

    const int ttx = tid % 24, tty = tid / 24;
    const int i0 = tty * 6, j0 = ttx * 6;
    ull acc[6][3];
#pragma unroll
    for (int i = 0; i < 6; i++)
#pragma unroll
        for (int jp = 0; jp < 3; jp++) acc[i][jp] = 0ULL;

#pragma unroll 2
    for (int kk = 0; kk < HDIM; kk++) {
        const float* qr = qT + kk * 146 + i0;
        const float* kr = kT + kk * 146 + j0;
        ull bp0 = *(const ull*)(kr + 0);
        ull bp1 = *(const ull*)(kr + 2);
        ull bp2 = *(const ull*)(kr + 4);
#pragma unroll
        for (int i = 0; i < 6; i++) {
            float a = qr[i];
            ull ad = pk(a, a);
            fma2(acc[i][0], ad, bp0);
            fma2(acc[i][1], ad, bp1);
            fma2(acc[i][2], ad, bp2);
        }
    }

    const float* mrow = mask + (size_t)b * NTOK * NTOK;
#pragma unroll
    for (int i = 0; i < 6; i++) {
        int n = i0 + i;
        const int*   pr = pidx + n * NTOK + j0;
        const float* mr = mrow + n * NTOK + j0;
        float* Sr = S + n * NTOK + j0;
#pragma unroll
        for (int jp = 0; jp < 3; jp++) {
            float2 pv = upk(acc[i][jp]);
            Sr[jp * 2 + 0] = pv.x + bcol[pr[jp * 2 + 0]] + mr[jp * 2 + 0];
            Sr[jp * 2 + 1] = pv.y + bcol[pr[jp * 2 + 1]] + mr[jp * 2 + 1];
        }
    }
    __syncthreads();

    const int wid = tid >> 5, lane = tid & 31;
    float invs[8];
#pragma unroll
    for (int i = 0; i < 8; i++) {
        int n = wid * 8 + i;
        float* Sr = S + n * NTOK;
        float mx = -1e30f;
        for (int c = lane; c < NTOK; c += 32) mx = fmaxf(mx, Sr[c]);
#pragma unroll
        for (int o = 16; o; o >>= 1) mx = fmaxf(mx, __shfl_xor_sync(0xffffffffu, mx, o));
        float sum = 0.f;
        for (int c = lane; c < NTOK; c += 32) {
            float e = __expf(Sr[c] - mx);
            Sr[c] = e;
            sum += e;
        }
#pragma unroll
        for (int o = 16; o; o >>= 1) sum += __shfl_xor_sync(0xffffffffu, sum, o);
        invs[i] = 1.0f / sum;
    }
    __syncwarp();

    ull o2[4] = {0ULL, 0ULL, 0ULL, 0ULL};
#pragma unroll 2
    for (int m = 0; m < NTOK; m += 4) {
        float v0 = Vv[(m + 0) * 33 + lane];
        float v1 = Vv[(m + 1) * 33 + lane];
        float v2 = Vv[(m + 2) * 33 + lane];
        float v3 = Vv[(m + 3) * 33 + lane];
        ull vd0 = pk(v0, v0), vd1 = pk(v1, v1), vd2 = pk(v2, v2), vd3 = pk(v3, v3);
#pragma unroll
        for (int p = 0; p < 4; p++) {
            int n0 = wid * 8 + 2 * p;
            float4 s0 = *(const float4*)&S[n0 * NTOK + m];
            float4 s1 = *(const float4*)&S[(n0 + 1) * NTOK + m];
            fma2(o2[p], pk(s0.x, s1.x), vd0);
            fma2(o2[p], pk(s0.y, s1.y), vd1);
            fma2(o2[p], pk(s0.z, s1.z), vd2);
            fma2(o2[p], pk(s0.w, s1.w), vd3);
        }
    }

    float* ob = outp + (size_t)(b * NW + w) * NTOK * DIM + h * HDIM + lane;
#pragma unroll
    for (int p = 0; p < 4; p++) {
        float2 pv = upk(o2[p]);
        int n0 = wid * 8 + 2 * p;
        ob[(size_t)n0 * DIM]       = pv.x * invs[2 * p];
        ob[(size_t)(n0 + 1) * DIM] = pv.y * invs[2 * p + 1];
    }
}

// ---------------------------------------------------------------------------
extern "C" void kernel_launch(void* const* d_in, const int* in_sizes, int n_in,
                              void* d_out, int out_size)
{
    const float* x    = (const float*)d_in[0];
    const float* mask = (const float*)d_in[1];
    const float* w1   = (const float*)d_in[2];
    const float* b1   = (const float*)d_in[3];
    const float* w2   = (const float*)d_in[4];
    const float* b2   = (const float*)d_in[5];
    const float* bt   = (const float*)d_in[6];
    const int*   pidx = (const int*)d_in[7];
    float* out = (float*)d_out;

    void *qkv_p, *att_p;
    cudaGetSymbolAddress(&qkv_p, g_qkv);
    cudaGetSymbolAddress(&att_p, g_att);
    float* qkv = (float*)qkv_p;
    float* att = (float*)att_p;

    cudaFuncSetAttribute(gemm_tc, cudaFuncAttributeMaxDynamicSharedMemorySize, G_SMEM_SZ);
    cudaFuncSetAttribute(attn_kernel, cudaFuncAttributeMaxDynamicSharedMemorySize, ATTN_SMEM);

    // QKV projection: 241920 x 576 x 192 (tcgen05 tf32)
    gemm_tc<<<MTILES, 256, G_SMEM_SZ>>>(x, w1, b1, qkv, 576);
    // fused attention per (b, w, h)
    attn_kernel<<<NW * BATCH * HEADS, 576, ATTN_SMEM>>>(qkv, bt, pidx, mask, att);
    // output projection: 241920 x 192 x 192 (tcgen05 tf32)
    gemm_tc<<<MTILES, 256, G_SMEM_SZ>>>(att, w2, b2, out, 192);
}

// round 7
// speedup vs baseline: 1.6607x; 1.6607x over previous
#include <cuda_runtime.h>
#include <cuda_bf16.h>
#include <cstdint>

// ---------------------------------------------------------------------------
// EarthAttention3D: B=2, nW=840, N=144, C=192, H=6, d=32
//   GEMMs on tcgen05 kind::tf32 when compiled arch-specific (sm_103a);
//   SIMT fp32 fallback body for plain compute_103 passes (tcgen05 is 'a'-only).
// ---------------------------------------------------------------------------

typedef unsigned long long ull;
typedef unsigned int u32;

#if defined(__CUDA_ARCH_FEAT_SM103_ALL) || defined(__CUDA_ARCH_FEAT_SM100_ALL) || \
    defined(__CUDA_ARCH_SPECIFIC__)
#define TC_OK 1
#else
#define TC_OK 0
#endif

#define NW     840
#define NTOK   144
#define DIM    192
#define HEADS  6
#define HDIM   32
#define BATCH  2
#define MTOT   (BATCH*NW*NTOK)          // 241920
#define MTILES (MTOT/128)               // 1890
#define TABLE  3312
#define QSCALE 0.17677669529663687f     // 32^-0.5

__device__ float g_qkv[(size_t)MTOT * 576];   // 557 MB scratch
__device__ float g_att[(size_t)MTOT * DIM];   // 186 MB scratch

// ---------------- generic helpers (valid on all targets) ----------------
__device__ __forceinline__ ull pk(float x, float y) {
    ull r; asm("mov.b64 %0,{%1,%2};" : "=l"(r) : "f"(x), "f"(y)); return r;
}
__device__ __forceinline__ float2 upk(ull a) {
    float2 f; asm("mov.b64 {%0,%1},%2;" : "=f"(f.x), "=f"(f.y) : "l"(a)); return f;
}
__device__ __forceinline__ void fma2(ull& d, ull a, ull b) {
    asm("fma.rn.f32x2 %0,%1,%2,%0;" : "+l"(d) : "l"(a), "l"(b));
}
__device__ __forceinline__ u32 smem_u32(const void* p) {
    u32 r; asm("{ .reg .u64 t; cvta.to.shared.u64 t, %1; cvt.u32.u64 %0, t; }"
               : "=r"(r) : "l"(p)); return r;
}

#if TC_OK
// ---------------- tcgen05 helpers (arch-specific targets only) -----------
__device__ __forceinline__ u32 cvt_tf32(float f) {
    u32 r; asm("cvt.rn.tf32.f32 %0, %1;" : "=r"(r) : "f"(f)); return r;
}
__device__ __forceinline__ void mbar_init(u32 mb, u32 cnt) {
    asm volatile("mbarrier.init.shared.b64 [%0], %1;" :: "r"(mb), "r"(cnt) : "memory");
}
__device__ __forceinline__ void mbar_wait(u32 mb, u32 par) {
    asm volatile(
        "{\n\t.reg .pred P;\n\t"
        "W%=:\n\t"
        "mbarrier.try_wait.parity.acquire.cta.shared::cta.b64 P, [%0], %1, 0x989680;\n\t"
        "@P bra D%=;\n\t"
        "bra W%=;\n\t"
        "D%=:\n\t}"
        :: "r"(mb), "r"(par) : "memory");
}
__device__ __forceinline__ ull mk_desc(u32 addr) {   // SW128 K-major, Blackwell v1
    return ((ull)2 << 61) | ((ull)1 << 46) | ((ull)64 << 32) | ((ull)1 << 16)
         | ((addr >> 4) & 0x3FFFull);
}

#define LDTM32(r, ta) \
    asm volatile( \
        "tcgen05.ld.sync.aligned.32x32b.x32.b32 " \
        "{%0, %1, %2, %3, %4, %5, %6, %7, " \
        " %8, %9, %10, %11, %12, %13, %14, %15, " \
        " %16, %17, %18, %19, %20, %21, %22, %23, " \
        " %24, %25, %26, %27, %28, %29, %30, %31}, [%32];" \
        : "=r"((r)[0]),  "=r"((r)[1]),  "=r"((r)[2]),  "=r"((r)[3]), \
          "=r"((r)[4]),  "=r"((r)[5]),  "=r"((r)[6]),  "=r"((r)[7]), \
          "=r"((r)[8]),  "=r"((r)[9]),  "=r"((r)[10]), "=r"((r)[11]), \
          "=r"((r)[12]), "=r"((r)[13]), "=r"((r)[14]), "=r"((r)[15]), \
          "=r"((r)[16]), "=r"((r)[17]), "=r"((r)[18]), "=r"((r)[19]), \
          "=r"((r)[20]), "=r"((r)[21]), "=r"((r)[22]), "=r"((r)[23]), \
          "=r"((r)[24]), "=r"((r)[25]), "=r"((r)[26]), "=r"((r)[27]), \
          "=r"((r)[28]), "=r"((r)[29]), "=r"((r)[30]), "=r"((r)[31]) \
        : "r"(ta))

// idesc: dtype=F32(1)<<4, atype=TF32(2)<<7, btype=TF32(2)<<10, N/8<<17, M/16<<24
static constexpr u32 IDESC_TF32 =
    (1u << 4) | (2u << 7) | (2u << 10) | ((64u / 8) << 17) | ((128u / 16) << 24);

__device__ __forceinline__ void mma_tf32(u32 dt, ull ad, ull bd, u32 en) {
    asm volatile(
        "{\n\t.reg .pred p;\n\t"
        "setp.ne.u32 p, %4, 0;\n\t"
        "tcgen05.mma.cta_group::1.kind::tf32 [%0], %1, %2, %3, {%5,%5,%5,%5}, p;\n\t}"
        :: "r"(dt), "l"(ad), "l"(bd), "r"(IDESC_TF32), "r"(en), "r"(0u) : "memory");
}
#endif  // TC_OK

// ---------------------------------------------------------------------------
// GEMM (NT): C[m,n] = A[m,:192] . W[n,:192] + bias[n]
// CTA: 128-row M tile, loops Ntot/64 N-subtiles. 256 threads.
// SMEM (from 1024-aligned base0):
//   +0 tmemptr | +16 mbar[2] | +1024 A(96KB, SW128 slabs of 128x32f)
//   +99328 W0(48KB) | +148480 W1(48KB)
// Pipeline per iter: issue MMA(it) -> prefetch W(it+1) LDGs into regs ->
//   wait MMA(it-1) -> 8-warp epilogue(it-1) -> STS W(it+1) -> fence+sync.
// ---------------------------------------------------------------------------
#define G_OFF_A   1024u
#define G_OFF_W0  99328u
#define G_OFF_W1  148480u
#define G_SMEM_SZ (197632 + 1024)

#if TC_OK
// 8-warp epilogue: warp w covers rows (w&3)*32+lane, cols (w>>2)*32..+31
__device__ __forceinline__ void gtc_epilogue8(u32 tmem, int bufsel, int nsub,
        float* __restrict__ C, const float* __restrict__ bias, int Ntot,
        int bm, int wid, int lane) {
    const int sp = wid & 3, ch = wid >> 2;
    u32 dt = tmem + (u32)(bufsel * 64 + ch * 32) + ((u32)sp << 21);
    u32 dr[32];
    asm volatile("tcgen05.fence::after_thread_sync;" ::: "memory");
    LDTM32(dr, dt);
    asm volatile("tcgen05.wait::ld.sync.aligned;" ::: "memory");
    asm volatile("tcgen05.fence::before_thread_sync;" ::: "memory");
    int m = bm + sp * 32 + lane;
    float* crow = C + (size_t)m * Ntot + nsub * 64 + ch * 32;
    const float4* b4 = (const float4*)(bias + nsub * 64 + ch * 32);
#pragma unroll
    for (int c = 0; c < 8; c++) {
        float4 bb = b4[c];
        float4 o;
        o.x = __uint_as_float(dr[4 * c + 0]) + bb.x;
        o.y = __uint_as_float(dr[4 * c + 1]) + bb.y;
        o.z = __uint_as_float(dr[4 * c + 2]) + bb.z;
        o.w = __uint_as_float(dr[4 * c + 3]) + bb.w;
        *(float4*)(crow + 4 * c) = o;
    }
}
#endif  // TC_OK

__global__ __launch_bounds__(256, 1) void gemm_tc(
    const float* __restrict__ A, const float* __restrict__ W,
    const float* __restrict__ bias, float* __restrict__ C, int Ntot)
{
    extern __shared__ char gsm_raw[];
    u32 sb_raw = smem_u32(gsm_raw);
    u32 sb0 = (sb_raw + 1023u) & ~1023u;
    char* gp = gsm_raw + (sb0 - sb_raw);

    const int tid = threadIdx.x;
    const int bm = blockIdx.x * 128;

#if TC_OK
    const int wid = tid >> 5, lane = tid & 31;
    const int niter = Ntot >> 6;

    if (wid == 0) {
        asm volatile("tcgen05.alloc.cta_group::1.sync.aligned.shared::cta.b32 [%0], %1;"
                     :: "r"(sb0), "r"(128u) : "memory");
        asm volatile("tcgen05.relinquish_alloc_permit.cta_group::1.sync.aligned;");
    }
    if (tid == 0) { mbar_init(sb0 + 16, 1); mbar_init(sb0 + 24, 1); }

    // ---- load A tile (128 x 192), tf32-round, SW128 slabs ----
    const float* Ab = A + (size_t)bm * 192;
#pragma unroll
    for (int j = 0; j < 24; j++) {
        int idx = tid + j * 256;
        int row = idx / 48, c4 = idx - row * 48;
        float4 v = *(const float4*)(Ab + row * 192 + c4 * 4);
        uint4 t;
        t.x = cvt_tf32(v.x); t.y = cvt_tf32(v.y);
        t.z = cvt_tf32(v.z); t.w = cvt_tf32(v.w);
        u32 bo = (u32)(row * 128 + (c4 & 7) * 16);
        bo ^= (bo >> 3) & 0x70;
        *(uint4*)(gp + G_OFF_A + (c4 >> 3) * 16384 + bo) = t;
    }
    // ---- load W subtile 0 (all 256 threads) ----
#pragma unroll
    for (int j = 0; j < 12; j++) {
        int idx = tid + j * 256;
        int row = idx / 48, c4 = idx - row * 48;
        float4 v = *(const float4*)(W + row * 192 + c4 * 4);
        uint4 t;
        t.x = cvt_tf32(v.x); t.y = cvt_tf32(v.y);
        t.z = cvt_tf32(v.z); t.w = cvt_tf32(v.w);
        u32 bo = (u32)(row * 128 + (c4 & 7) * 16);
        bo ^= (bo >> 3) & 0x70;
        *(uint4*)(gp + G_OFF_W0 + (c4 >> 3) * 8192 + bo) = t;
    }
    asm volatile("fence.proxy.async.shared::cta;" ::: "memory");
    __syncthreads();

    u32 tmem;
    asm("ld.shared.b32 %0, [%1];" : "=r"(tmem) : "r"(sb0));

    const ull descA = mk_desc(sb0 + G_OFF_A);
    u32 ph0 = 0, ph1 = 0;

    for (int it = 0; it < niter; it++) {
        const int buf = it & 1;
        // ---- issue MMA(it) on D[buf] reading W[buf] ----
        if (tid == 0) {
            ull descW = mk_desc(sb0 + (buf ? G_OFF_W1 : G_OFF_W0));
            u32 dtm = tmem + buf * 64;
#pragma unroll
            for (int k = 0; k < 24; k++)
                mma_tf32(dtm, descA + (k >> 2) * 1024 + (k & 3) * 2,
                              descW + (k >> 2) * 512 + (k & 3) * 2, (u32)(k > 0));
            asm volatile(
                "tcgen05.commit.cta_group::1.mbarrier::arrive::one.shared::cluster.b64 [%0];"
                :: "r"(sb0 + 16 + buf * 8) : "memory");
        }

        // ---- prefetch W(it+1) into registers (LGDs issued before the wait) ----
        const bool havew = (it + 1 < niter);
        float4 wreg[12];
        if (havew) {
            const float* ws = W + (size_t)(it + 1) * 64 * 192;
#pragma unroll
            for (int j = 0; j < 12; j++) {
                int idx = tid + j * 256;
                int row = idx / 48, c4 = idx - row * 48;
                wreg[j] = *(const float4*)(ws + row * 192 + c4 * 4);
            }
        }

        // ---- wait for MMA(it-1), run its epilogue on all 8 warps ----
        if (it > 0) {
            const int pb = buf ^ 1;
            if (pb == 0) { mbar_wait(sb0 + 16, ph0); ph0 ^= 1; }
            else         { mbar_wait(sb0 + 24, ph1); ph1 ^= 1; }
            gtc_epilogue8(tmem, pb, it - 1, C, bias, Ntot, bm, wid, lane);
        }

        // ---- commit prefetched W(it+1) to SMEM buffer buf^1 ----
        if (havew) {
            char* wdst = gp + (buf ? G_OFF_W0 : G_OFF_W1);
#pragma unroll
            for (int j = 0; j < 12; j++) {
                int idx = tid + j * 256;
                int row = idx / 48, c4 = idx - row * 48;
                uint4 t;
                t.x = cvt_tf32(wreg[j].x); t.y = cvt_tf32(wreg[j].y);
                t.z = cvt_tf32(wreg[j].z); t.w = cvt_tf32(wreg[j].w);
                u32 bo = (u32)(row * 128 + (c4 & 7) * 16);
                bo ^= (bo >> 3) & 0x70;
                *(uint4*)(wdst + (c4 >> 3) * 8192 + bo) = t;
            }
        }
        asm volatile("fence.proxy.async.shared::cta;" ::: "memory");
        __syncthreads();
    }
    // ---- final epilogue ----
    {
        const int lb = (niter - 1) & 1;
        if (lb == 0) mbar_wait(sb0 + 16, ph0);
        else         mbar_wait(sb0 + 24, ph1);
        gtc_epilogue8(tmem, lb, niter - 1, C, bias, Ntot, bm, wid, lane);
    }
    __syncthreads();
    if (wid == 0)
        asm volatile("tcgen05.dealloc.cta_group::1.sync.aligned.b32 %0, %1;"
                     :: "r"(tmem), "r"(128u));

#else  // --------- SIMT fp32 fallback (plain compute_103 pass) ----------
    float* As = (float*)gp;
    const float* Ab = A + (size_t)bm * 192;
    for (int i = tid; i < 128 * 48; i += 256)
        ((float4*)As)[i] = ((const float4*)Ab)[i];
    __syncthreads();
    for (int idx = tid; idx < 128 * Ntot; idx += 256) {
        int col = idx >> 7, row = idx & 127;
        const float4* ar = (const float4*)(As + row * 192);
        const float4* wr = (const float4*)(W + (size_t)col * 192);
        float s = 0.f;
#pragma unroll 8
        for (int k = 0; k < 48; k++) {
            float4 a = ar[k], w = wr[k];
            s += a.x * w.x + a.y * w.y + a.z * w.z + a.w * w.w;
        }
        C[(size_t)(bm + row) * Ntot + col] = s + bias[col];
    }
#endif
}

// ---------------------------------------------------------------------------
// Attention per (b, w, h). 576 threads, full-S in SMEM. (unchanged)
// ---------------------------------------------------------------------------
#define OFS_QT 20736
#define OFS_KT (OFS_QT + 32*146)
#define OFS_V  (OFS_KT + 32*146)
#define OFS_BC (OFS_V + 144*33)
#define ATTN_SMEM ((OFS_BC + TABLE) * 4)

__global__ __launch_bounds__(576, 1) void attn_kernel(
    const float* __restrict__ qkv, const float* __restrict__ bias_table,
    const int* __restrict__ pidx, const float* __restrict__ mask,
    float* __restrict__ outp)
{
    extern __shared__ __align__(16) float sm[];
    float* S    = sm;
    float* qT   = sm + OFS_QT;
    float* kT   = sm + OFS_KT;
    float* Vv   = sm + OFS_V;
    float* bcol = sm + OFS_BC;

    const int tid = threadIdx.x;
    const int bx  = blockIdx.x;
    const int w = bx / 12;
    const int rr = bx - w * 12;
    const int b = rr / 6;
    const int h = rr - b * 6;

    const size_t base = (size_t)(b * NW + w) * NTOK * 576 + h * HDIM;
    const float* qg = qkv + base;
    const float* kg = qg + 192;
    const float* vg = qg + 384;

    for (int idx = tid; idx < NTOK * HDIM; idx += 576) {
        int n = idx >> 5, dd = idx & 31;
        qT[dd * 146 + n] = qg[(size_t)n * 576 + dd] * QSCALE;
        kT[dd * 146 + n] = kg[(size_t)n * 576 + dd];
        Vv[n * 33 + dd]  = vg[(size_t)n * 576 + dd];
    }
    for (int i = tid; i < TABLE; i += 576)
        bcol[i] = bias_table[(size_t)i * (NW * HEADS) + w * HEADS + h];
    __syncthreads();

    const int ttx = tid % 24, tty = tid / 24;
    const int i0 = tty * 6, j0 = ttx * 6;
    ull acc[6][3];
#pragma unroll
    for (int i = 0; i < 6; i++)
#pragma unroll
        for (int jp = 0; jp < 3; jp++) acc[i][jp] = 0ULL;

#pragma unroll 2
    for (int kk = 0; kk < HDIM; kk++) {
        const float* qr = qT + kk * 146 + i0;
        const float* kr = kT + kk * 146 + j0;
        ull bp0 = *(const ull*)(kr + 0);
        ull bp1 = *(const ull*)(kr + 2);
        ull bp2 = *(const ull*)(kr + 4);
#pragma unroll
        for (int i = 0; i < 6; i++) {
            float a = qr[i];
            ull ad = pk(a, a);
            fma2(acc[i][0], ad, bp0);
            fma2(acc[i][1], ad, bp1);
            fma2(acc[i][2], ad, bp2);
        }
    }

    const float* mrow = mask + (size_t)b * NTOK * NTOK;
#pragma unroll
    for (int i = 0; i < 6; i++) {
        int n = i0 + i;
        const int*   pr = pidx + n * NTOK + j0;
        const float* mr = mrow + n * NTOK + j0;
        float* Sr = S + n * NTOK + j0;
#pragma unroll
        for (int jp = 0; jp < 3; jp++) {
            float2 pv = upk(acc[i][jp]);
            Sr[jp * 2 + 0] = pv.x + bcol[pr[jp * 2 + 0]] + mr[jp * 2 + 0];
            Sr[jp * 2 + 1] = pv.y + bcol[pr[jp * 2 + 1]] + mr[jp * 2 + 1];
        }
    }
    __syncthreads();

    const int wid = tid >> 5, lane = tid & 31;
    float invs[8];
#pragma unroll
    for (int i = 0; i < 8; i++) {
        int n = wid * 8 + i;
        float* Sr = S + n * NTOK;
        float mx = -1e30f;
        for (int c = lane; c < NTOK; c += 32) mx = fmaxf(mx, Sr[c]);
#pragma unroll
        for (int o = 16; o; o >>= 1) mx = fmaxf(mx, __shfl_xor_sync(0xffffffffu, mx, o));
        float sum = 0.f;
        for (int c = lane; c < NTOK; c += 32) {
            float e = __expf(Sr[c] - mx);
            Sr[c] = e;
            sum += e;
        }
#pragma unroll
        for (int o = 16; o; o >>= 1) sum += __shfl_xor_sync(0xffffffffu, sum, o);
        invs[i] = 1.0f / sum;
    }
    __syncwarp();

    ull o2[4] = {0ULL, 0ULL, 0ULL, 0ULL};
#pragma unroll 2
    for (int m = 0; m < NTOK; m += 4) {
        float v0 = Vv[(m + 0) * 33 + lane];
        float v1 = Vv[(m + 1) * 33 + lane];
        float v2 = Vv[(m + 2) * 33 + lane];
        float v3 = Vv[(m + 3) * 33 + lane];
        ull vd0 = pk(v0, v0), vd1 = pk(v1, v1), vd2 = pk(v2, v2), vd3 = pk(v3, v3);
#pragma unroll
        for (int p = 0; p < 4; p++) {
            int n0 = wid * 8 + 2 * p;
            float4 s0 = *(const float4*)&S[n0 * NTOK + m];
            float4 s1 = *(const float4*)&S[(n0 + 1) * NTOK + m];
            fma2(o2[p], pk(s0.x, s1.x), vd0);
            fma2(o2[p], pk(s0.y, s1.y), vd1);
            fma2(o2[p], pk(s0.z, s1.z), vd2);
            fma2(o2[p], pk(s0.w, s1.w), vd3);
        }
    }

    float* ob = outp + (size_t)(b * NW + w) * NTOK * DIM + h * HDIM + lane;
#pragma unroll
    for (int p = 0; p < 4; p++) {
        float2 pv = upk(o2[p]);
        int n0 = wid * 8 + 2 * p;
        ob[(size_t)n0 * DIM]       = pv.x * invs[2 * p];
        ob[(size_t)(n0 + 1) * DIM] = pv.y * invs[2 * p + 1];
    }
}

// ---------------------------------------------------------------------------
extern "C" void kernel_launch(void* const* d_in, const int* in_sizes, int n_in,
                              void* d_out, int out_size)
{
    const float* x    = (const float*)d_in[0];
    const float* mask = (const float*)d_in[1];
    const float* w1   = (const float*)d_in[2];
    const float* b1   = (const float*)d_in[3];
    const float* w2   = (const float*)d_in[4];
    const float* b2   = (const float*)d_in[5];
    const float* bt   = (const float*)d_in[6];
    const int*   pidx = (const int*)d_in[7];
    float* out = (float*)d_out;

    void *qkv_p, *att_p;
    cudaGetSymbolAddress(&qkv_p, g_qkv);
    cudaGetSymbolAddress(&att_p, g_att);
    float* qkv = (float*)qkv_p;
    float* att = (float*)att_p;

    cudaFuncSetAttribute(gemm_tc, cudaFuncAttributeMaxDynamicSharedMemorySize, G_SMEM_SZ);
    cudaFuncSetAttribute(attn_kernel, cudaFuncAttributeMaxDynamicSharedMemorySize, ATTN_SMEM);

    // QKV projection: 241920 x 576 x 192 (tcgen05 tf32)
    gemm_tc<<<MTILES, 256, G_SMEM_SZ>>>(x, w1, b1, qkv, 576);
    // fused attention per (b, w, h)
    attn_kernel<<<NW * BATCH * HEADS, 576, ATTN_SMEM>>>(qkv, bt, pidx, mask, att);
    // output projection: 241920 x 192 x 192 (tcgen05 tf32)
    gemm_tc<<<MTILES, 256, G_SMEM_SZ>>>(att, w2, b2, out, 192);
}

// round 8
// speedup vs baseline: 2.4543x; 1.4778x over previous
#include <cuda_runtime.h>
#include <cuda_bf16.h>
#include <cstdint>

// ---------------------------------------------------------------------------
// EarthAttention3D: B=2, nW=840, N=144, C=192, H=6, d=32
//   QKV/proj GEMMs + attention all on tcgen05 kind::tf32 (sm_103a cubin);
//   SIMT fallback bodies for the plain compute_103 ptxas pass.
// ---------------------------------------------------------------------------

typedef unsigned long long ull;
typedef unsigned int u32;

#if defined(__CUDA_ARCH_FEAT_SM103_ALL) || defined(__CUDA_ARCH_FEAT_SM100_ALL) || \
    defined(__CUDA_ARCH_SPECIFIC__)
#define TC_OK 1
#else
#define TC_OK 0
#endif

#define NW     840
#define NTOK   144
#define DIM    192
#define HEADS  6
#define HDIM   32
#define BATCH  2
#define MTOT   (BATCH*NW*NTOK)          // 241920
#define MTILES (MTOT/128)               // 1890
#define TABLE  3312
#define QSCALE 0.17677669529663687f     // 32^-0.5

__device__ float g_qkv[(size_t)MTOT * 576];   // 557 MB scratch
__device__ float g_att[(size_t)MTOT * DIM];   // 186 MB scratch

// ---------------- generic helpers ----------------
__device__ __forceinline__ u32 smem_u32(const void* p) {
    u32 r; asm("{ .reg .u64 t; cvta.to.shared.u64 t, %1; cvt.u32.u64 %0, t; }"
               : "=r"(r) : "l"(p)); return r;
}

#if TC_OK
// ---------------- tcgen05 helpers (arch-specific only) -----------
__device__ __forceinline__ u32 cvt_tf32(float f) {
    u32 r; asm("cvt.rn.tf32.f32 %0, %1;" : "=r"(r) : "f"(f)); return r;
}
__device__ __forceinline__ void mbar_init(u32 mb, u32 cnt) {
    asm volatile("mbarrier.init.shared.b64 [%0], %1;" :: "r"(mb), "r"(cnt) : "memory");
}
__device__ __forceinline__ void mbar_wait(u32 mb, u32 par) {
    asm volatile(
        "{\n\t.reg .pred P;\n\t"
        "W%=:\n\t"
        "mbarrier.try_wait.parity.acquire.cta.shared::cta.b64 P, [%0], %1, 0x989680;\n\t"
        "@P bra D%=;\n\t"
        "bra W%=;\n\t"
        "D%=:\n\t}"
        :: "r"(mb), "r"(par) : "memory");
}
__device__ __forceinline__ ull mk_desc(u32 addr) {   // SW128 K-major, Blackwell v1
    return ((ull)2 << 61) | ((ull)1 << 46) | ((ull)64 << 32) | ((ull)1 << 16)
         | ((addr >> 4) & 0x3FFFull);
}

#define LDTM32(r, ta) \
    asm volatile( \
        "tcgen05.ld.sync.aligned.32x32b.x32.b32 " \
        "{%0, %1, %2, %3, %4, %5, %6, %7, " \
        " %8, %9, %10, %11, %12, %13, %14, %15, " \
        " %16, %17, %18, %19, %20, %21, %22, %23, " \
        " %24, %25, %26, %27, %28, %29, %30, %31}, [%32];" \
        : "=r"((r)[0]),  "=r"((r)[1]),  "=r"((r)[2]),  "=r"((r)[3]), \
          "=r"((r)[4]),  "=r"((r)[5]),  "=r"((r)[6]),  "=r"((r)[7]), \
          "=r"((r)[8]),  "=r"((r)[9]),  "=r"((r)[10]), "=r"((r)[11]), \
          "=r"((r)[12]), "=r"((r)[13]), "=r"((r)[14]), "=r"((r)[15]), \
          "=r"((r)[16]), "=r"((r)[17]), "=r"((r)[18]), "=r"((r)[19]), \
          "=r"((r)[20]), "=r"((r)[21]), "=r"((r)[22]), "=r"((r)[23]), \
          "=r"((r)[24]), "=r"((r)[25]), "=r"((r)[26]), "=r"((r)[27]), \
          "=r"((r)[28]), "=r"((r)[29]), "=r"((r)[30]), "=r"((r)[31]) \
        : "r"(ta))

#define TMWAIT_LD()  asm volatile("tcgen05.wait::ld.sync.aligned;" ::: "memory")
#define TMF_AFTER()  asm volatile("tcgen05.fence::after_thread_sync;" ::: "memory")
#define TMF_BEFORE() asm volatile("tcgen05.fence::before_thread_sync;" ::: "memory")

static constexpr u32 IDESC_G  = (1u<<4)|(2u<<7)|(2u<<10)|((64u/8)<<17)|((128u/16)<<24);
static constexpr u32 IDESC_S  = (1u<<4)|(2u<<7)|(2u<<10)|((144u/8)<<17)|((128u/16)<<24);
static constexpr u32 IDESC_PV = (1u<<4)|(2u<<7)|(2u<<10)|((32u/8)<<17)|((128u/16)<<24);

__device__ __forceinline__ void mma_tf32(u32 dt, ull ad, ull bd, u32 idesc, u32 en) {
    asm volatile(
        "{\n\t.reg .pred p;\n\t"
        "setp.ne.u32 p, %4, 0;\n\t"
        "tcgen05.mma.cta_group::1.kind::tf32 [%0], %1, %2, %3, {%5,%5,%5,%5}, p;\n\t}"
        :: "r"(dt), "l"(ad), "l"(bd), "r"(idesc), "r"(en), "r"(0u) : "memory");
}
#endif  // TC_OK

// ---------------------------------------------------------------------------
// GEMM (NT) via tcgen05 tf32 (unchanged from round 7)
// ---------------------------------------------------------------------------
#define G_OFF_A   1024u
#define G_OFF_W0  99328u
#define G_OFF_W1  148480u
#define G_SMEM_SZ (197632 + 1024)

#if TC_OK
__device__ __forceinline__ void gtc_epilogue8(u32 tmem, int bufsel, int nsub,
        float* __restrict__ C, const float* __restrict__ bias, int Ntot,
        int bm, int wid, int lane) {
    const int sp = wid & 3, ch = wid >> 2;
    u32 dt = tmem + (u32)(bufsel * 64 + ch * 32) + ((u32)sp << 21);
    u32 dr[32];
    TMF_AFTER();
    LDTM32(dr, dt);
    TMWAIT_LD();
    TMF_BEFORE();
    int m = bm + sp * 32 + lane;
    float* crow = C + (size_t)m * Ntot + nsub * 64 + ch * 32;
    const float4* b4 = (const float4*)(bias + nsub * 64 + ch * 32);
#pragma unroll
    for (int c = 0; c < 8; c++) {
        float4 bb = b4[c];
        float4 o;
        o.x = __uint_as_float(dr[4 * c + 0]) + bb.x;
        o.y = __uint_as_float(dr[4 * c + 1]) + bb.y;
        o.z = __uint_as_float(dr[4 * c + 2]) + bb.z;
        o.w = __uint_as_float(dr[4 * c + 3]) + bb.w;
        *(float4*)(crow + 4 * c) = o;
    }
}
#endif  // TC_OK

__global__ __launch_bounds__(256, 1) void gemm_tc(
    const float* __restrict__ A, const float* __restrict__ W,
    const float* __restrict__ bias, float* __restrict__ C, int Ntot)
{
    extern __shared__ char gsm_raw[];
    u32 sb_raw = smem_u32(gsm_raw);
    u32 sb0 = (sb_raw + 1023u) & ~1023u;
    char* gp = gsm_raw + (sb0 - sb_raw);

    const int tid = threadIdx.x;
    const int bm = blockIdx.x * 128;

#if TC_OK
    const int wid = tid >> 5, lane = tid & 31;
    const int niter = Ntot >> 6;

    if (wid == 0) {
        asm volatile("tcgen05.alloc.cta_group::1.sync.aligned.shared::cta.b32 [%0], %1;"
                     :: "r"(sb0), "r"(128u) : "memory");
        asm volatile("tcgen05.relinquish_alloc_permit.cta_group::1.sync.aligned;");
    }
    if (tid == 0) { mbar_init(sb0 + 16, 1); mbar_init(sb0 + 24, 1); }

    const float* Ab = A + (size_t)bm * 192;
#pragma unroll
    for (int j = 0; j < 24; j++) {
        int idx = tid + j * 256;
        int row = idx / 48, c4 = idx - row * 48;
        float4 v = *(const float4*)(Ab + row * 192 + c4 * 4);
        uint4 t;
        t.x = cvt_tf32(v.x); t.y = cvt_tf32(v.y);
        t.z = cvt_tf32(v.z); t.w = cvt_tf32(v.w);
        u32 bo = (u32)(row * 128 + (c4 & 7) * 16);
        bo ^= (bo >> 3) & 0x70;
        *(uint4*)(gp + G_OFF_A + (c4 >> 3) * 16384 + bo) = t;
    }
#pragma unroll
    for (int j = 0; j < 12; j++) {
        int idx = tid + j * 256;
        int row = idx / 48, c4 = idx - row * 48;
        float4 v = *(const float4*)(W + row * 192 + c4 * 4);
        uint4 t;
        t.x = cvt_tf32(v.x); t.y = cvt_tf32(v.y);
        t.z = cvt_tf32(v.z); t.w = cvt_tf32(v.w);
        u32 bo = (u32)(row * 128 + (c4 & 7) * 16);
        bo ^= (bo >> 3) & 0x70;
        *(uint4*)(gp + G_OFF_W0 + (c4 >> 3) * 8192 + bo) = t;
    }
    asm volatile("fence.proxy.async.shared::cta;" ::: "memory");
    __syncthreads();

    u32 tmem;
    asm("ld.shared.b32 %0, [%1];" : "=r"(tmem) : "r"(sb0));

    const ull descA = mk_desc(sb0 + G_OFF_A);
    u32 ph0 = 0, ph1 = 0;

    for (int it = 0; it < niter; it++) {
        const int buf = it & 1;
        if (tid == 0) {
            ull descW = mk_desc(sb0 + (buf ? G_OFF_W1 : G_OFF_W0));
            u32 dtm = tmem + buf * 64;
#pragma unroll
            for (int k = 0; k < 24; k++)
                mma_tf32(dtm, descA + (k >> 2) * 1024 + (k & 3) * 2,
                              descW + (k >> 2) * 512 + (k & 3) * 2, IDESC_G, (u32)(k > 0));
            asm volatile(
                "tcgen05.commit.cta_group::1.mbarrier::arrive::one.shared::cluster.b64 [%0];"
                :: "r"(sb0 + 16 + buf * 8) : "memory");
        }

        const bool havew = (it + 1 < niter);
        float4 wreg[12];
        if (havew) {
            const float* ws = W + (size_t)(it + 1) * 64 * 192;
#pragma unroll
            for (int j = 0; j < 12; j++) {
                int idx = tid + j * 256;
                int row = idx / 48, c4 = idx - row * 48;
                wreg[j] = *(const float4*)(ws + row * 192 + c4 * 4);
            }
        }

        if (it > 0) {
            const int pb = buf ^ 1;
            if (pb == 0) { mbar_wait(sb0 + 16, ph0); ph0 ^= 1; }
            else         { mbar_wait(sb0 + 24, ph1); ph1 ^= 1; }
            gtc_epilogue8(tmem, pb, it - 1, C, bias, Ntot, bm, wid, lane);
        }

        if (havew) {
            char* wdst = gp + (buf ? G_OFF_W0 : G_OFF_W1);
#pragma unroll
            for (int j = 0; j < 12; j++) {
                int idx = tid + j * 256;
                int row = idx / 48, c4 = idx - row * 48;
                uint4 t;
                t.x = cvt_tf32(wreg[j].x); t.y = cvt_tf32(wreg[j].y);
                t.z = cvt_tf32(wreg[j].z); t.w = cvt_tf32(wreg[j].w);
                u32 bo = (u32)(row * 128 + (c4 & 7) * 16);
                bo ^= (bo >> 3) & 0x70;
                *(uint4*)(wdst + (c4 >> 3) * 8192 + bo) = t;
            }
        }
        asm volatile("fence.proxy.async.shared::cta;" ::: "memory");
        __syncthreads();
    }
    {
        const int lb = (niter - 1) & 1;
        if (lb == 0) mbar_wait(sb0 + 16, ph0);
        else         mbar_wait(sb0 + 24, ph1);
        gtc_epilogue8(tmem, lb, niter - 1, C, bias, Ntot, bm, wid, lane);
    }
    __syncthreads();
    if (wid == 0)
        asm volatile("tcgen05.dealloc.cta_group::1.sync.aligned.b32 %0, %1;"
                     :: "r"(tmem), "r"(128u));

#else  // --------- SIMT fp32 fallback ----------
    float* As = (float*)gp;
    const float* Ab = A + (size_t)bm * 192;
    for (int i = tid; i < 128 * 48; i += 256)
        ((float4*)As)[i] = ((const float4*)Ab)[i];
    __syncthreads();
    for (int idx = tid; idx < 128 * Ntot; idx += 256) {
        int col = idx >> 7, row = idx & 127;
        const float4* ar = (const float4*)(As + row * 192);
        const float4* wr = (const float4*)(W + (size_t)col * 192);
        float s = 0.f;
#pragma unroll 8
        for (int k = 0; k < 48; k++) {
            float4 a = ar[k], w = wr[k];
            s += a.x * w.x + a.y * w.y + a.z * w.z + a.w * w.w;
        }
        C[(size_t)(bm + row) * Ntot + col] = s + bias[col];
    }
#endif
}

// ---------------------------------------------------------------------------
// tcgen05 attention: one CTA per (b,w), 512 threads, 6 heads sequential.
// S^T = k q^T (M=144 keys via 2x M128 MMAs, N=144 queries, K=32)
// stage S^T -> P slabs (K-major SW128), 16-warp softmax (bias arithmetic,
// mask LDG coalesced), PV: A=P (K=160, last 16 zeroed via VT), B=V^T.
// SMEM layout (1024-aligned base):
//   0: tmem ptr, 16: mbar
//   P_OFF  = 1024   : 5 slabs x 18432 = 92160  (k tile @slab0, q tile @slab1)
//   VT_OFF = 93184  : 5 slabs x 4096  = 20480
//   BC_OFF = 113664 : bias cache 6*3312*4 = 79488
//   INV_OFF= 193152 : 1/rowsum, 144*4
// ---------------------------------------------------------------------------
#define A_P_OFF   1024u
#define A_VT_OFF  93184u
#define A_BC_OFF  113664u
#define A_INV_OFF 193152u
#define ATTN2_SMEM (193152 + 1024 + 1024)

__global__ __launch_bounds__(512, 1) void attn_tc(
    const float* __restrict__ qkv, const float* __restrict__ bias_table,
    const float* __restrict__ mask, float* __restrict__ outp)
{
    extern __shared__ char asm_raw[];
    u32 sb_raw = smem_u32(asm_raw);
    u32 sb0 = (sb_raw + 1023u) & ~1023u;
    char* gp = asm_raw + (sb0 - sb_raw);

    const int tid = threadIdx.x;
    const int w = blockIdx.x >> 1;
    const int b = blockIdx.x & 1;
    const float* gq = qkv + (size_t)(b * NW + w) * NTOK * 576;
    const float* maskb = mask + (size_t)b * NTOK * NTOK;
    float* ga = outp + (size_t)(b * NW + w) * NTOK * DIM;

#if TC_OK
    const int wid = tid >> 5, lane = tid & 31;

    if (wid == 0) {
        asm volatile("tcgen05.alloc.cta_group::1.sync.aligned.shared::cta.b32 [%0], %1;"
                     :: "r"(sb0), "r"(512u) : "memory");
        asm volatile("tcgen05.relinquish_alloc_permit.cta_group::1.sync.aligned;");
    }
    if (tid == 0) mbar_init(sb0 + 16, 1);

    // ---- bias cache for all 6 heads: bc[i*6+h] ----
    {
        float* bc = (float*)(gp + A_BC_OFF);
        for (int idx = tid; idx < TABLE * 6; idx += 512) {
            int i = idx / 6, hh = idx - i * 6;
            bc[idx] = bias_table[(size_t)i * (NW * HEADS) + w * HEADS + hh];
        }
    }
    // per-lane column part of bias index, per 32-col chunk
    int cp[5];
#pragma unroll
    for (int cc = 0; cc < 5; cc++) {
        int c = cc * 32 + lane;
        if (c < NTOK) {
            int jz = c / 72, rm = c - jz * 72;
            int jh = rm / 12, jw = rm - jh * 12;
            cp[cc] = jz * 1656 + jh * 138 - jw;
        } else cp[cc] = 0;
    }
    __syncthreads();

    u32 tmem;
    asm("ld.shared.b32 %0, [%1];" : "=r"(tmem) : "r"(sb0));
    const float* bcf = (const float*)(gp + A_BC_OFF);
    float* invp = (float*)(gp + A_INV_OFF);
    u32 mph = 0;

    for (int h = 0; h < HEADS; h++) {
        const int hb = h * HDIM;
        // ---- stage k (slab0) and q (slab1, scaled), tf32+SW128 ----
        for (int idx = tid; idx < 1152; idx += 512) {
            int row = idx >> 3, c4 = idx & 7;
            const float* src = gq + (size_t)row * 576 + 192 + hb + c4 * 4;
            float4 v = *(const float4*)src;
            uint4 t;
            t.x = cvt_tf32(v.x); t.y = cvt_tf32(v.y);
            t.z = cvt_tf32(v.z); t.w = cvt_tf32(v.w);
            u32 bo = (u32)(row * 128 + c4 * 16);
            bo ^= (bo >> 3) & 0x70;
            *(uint4*)(gp + A_P_OFF + bo) = t;
        }
        for (int idx = tid; idx < 1152; idx += 512) {
            int row = idx >> 3, c4 = idx & 7;
            const float* src = gq + (size_t)row * 576 + hb + c4 * 4;
            float4 v = *(const float4*)src;
            uint4 t;
            t.x = cvt_tf32(v.x * QSCALE); t.y = cvt_tf32(v.y * QSCALE);
            t.z = cvt_tf32(v.z * QSCALE); t.w = cvt_tf32(v.w * QSCALE);
            u32 bo = (u32)(row * 128 + c4 * 16);
            bo ^= (bo >> 3) & 0x70;
            *(uint4*)(gp + A_P_OFF + 18432 + bo) = t;
        }
        // ---- stage V^T (5 slabs) + zero pad cols 144..159 ----
        for (int idx = tid; idx < 1152; idx += 512) {
            int m = idx % NTOK, d4 = idx / NTOK;       // d4 in 0..7
            const float* src = gq + (size_t)m * 576 + 384 + hb + d4 * 4;
            float4 v = *(const float4*)src;
            char* slab = gp + A_VT_OFF + (m >> 5) * 4096;
            u32 colb = (u32)((m & 31) * 4);
#pragma unroll
            for (int j = 0; j < 4; j++) {
                u32 bo = (u32)((d4 * 4 + j) * 128) + colb;
                bo ^= (bo >> 3) & 0x70;
                float val = j == 0 ? v.x : (j == 1 ? v.y : (j == 2 ? v.z : v.w));
                *(u32*)(slab + bo) = cvt_tf32(val);
            }
        }
        if (tid < 512) {
            int d = tid >> 4, mm = 16 + (tid & 15);    // m = 144..159 -> col 16..31
            u32 bo = (u32)(d * 128 + mm * 4);
            bo ^= (bo >> 3) & 0x70;
            *(u32*)(gp + A_VT_OFF + 4 * 4096 + bo) = 0u;
        }
        asm volatile("fence.proxy.async.shared::cta;" ::: "memory");
        __syncthreads();

        // ---- S^T MMAs: D1 @col0 (keys 0..127), D2 @col144 (keys 16..143) ----
        if (tid == 0) {
            ull kd = mk_desc(sb0 + A_P_OFF);
            ull qd = mk_desc(sb0 + A_P_OFF + 18432);
#pragma unroll
            for (int c = 0; c < 4; c++)
                mma_tf32(tmem, kd + c * 2, qd + c * 2, IDESC_S, (u32)(c > 0));
#pragma unroll
            for (int c = 0; c < 4; c++)
                mma_tf32(tmem + 144, kd + 128 + c * 2, qd + c * 2, IDESC_S, (u32)(c > 0));
            asm volatile(
                "tcgen05.commit.cta_group::1.mbarrier::arrive::one.shared::cluster.b64 [%0];"
                :: "r"(sb0 + 16) : "memory");
        }
        mbar_wait(sb0 + 16, mph & 1); mph++;
        TMF_AFTER();

        // ---- stage S^T -> P slabs (transpose; lane = key) ----
        if (wid < 4) {
            char* ps = gp + A_P_OFF + wid * 18432;
#pragma unroll
            for (int cc = 0; cc < 5; cc++) {
                const int nq = (cc < 4) ? 32 : 16;
                u32 dr[32];
                LDTM32(dr, tmem + cc * 32 + ((u32)wid << 21));
                TMWAIT_LD();
#pragma unroll
                for (int j = 0; j < 32; j++) {
                    if (j < nq) {
                        u32 o = (u32)((cc * 32 + j) * 128 + lane * 4);
                        o ^= (o >> 3) & 0x70;
                        *(u32*)(ps + o) = dr[j];
                    }
                }
            }
            if (wid == 3) {   // keys 128..143 live in D2 lanes 112..127
                char* p4 = gp + A_P_OFF + 4 * 18432;
#pragma unroll
                for (int cc = 0; cc < 5; cc++) {
                    const int nq = (cc < 4) ? 32 : 16;
                    u32 dr[32];
                    LDTM32(dr, tmem + 144 + cc * 32 + (3u << 21));
                    TMWAIT_LD();
                    if (lane >= 16) {
#pragma unroll
                        for (int j = 0; j < 32; j++) {
                            if (j < nq) {
                                u32 o = (u32)((cc * 32 + j) * 128 + (lane - 16) * 4);
                                o ^= (o >> 3) & 0x70;
                                *(u32*)(p4 + o) = dr[j];
                            }
                        }
                    }
                }
            }
            TMF_BEFORE();
        }
        __syncthreads();

        // ---- softmax rows (16 warps x 9 rows), in-place in P slabs ----
#pragma unroll
        for (int rr = 0; rr < 9; rr++) {
            const int r = wid * 9 + rr;
            int iz = r / 72, rm = r - iz * 72;
            int ih = rm / 12, iw = rm - ih * 12;
            const int rp = iz * 828 + ih * 23 + iw + 11;
            const float* mrow = maskb + r * NTOK;
            float vals[5];
            float mx = -3.0e38f;
#pragma unroll
            for (int cc = 0; cc < 5; cc++) {
                int c = cc * 32 + lane;
                if (c < NTOK) {
                    u32 o = (u32)(r * 128 + (c & 31) * 4);
                    o ^= (o >> 3) & 0x70;
                    float a = *(const float*)(gp + A_P_OFF + cc * 18432 + o);
                    a += bcf[(rp + cp[cc]) * 6 + h] + __ldg(mrow + c);
                    vals[cc] = a;
                    mx = fmaxf(mx, a);
                } else vals[cc] = -3.0e38f;
            }
#pragma unroll
            for (int o2 = 16; o2; o2 >>= 1) mx = fmaxf(mx, __shfl_xor_sync(0xffffffffu, mx, o2));
            float sum = 0.f;
#pragma unroll
            for (int cc = 0; cc < 5; cc++) {
                int c = cc * 32 + lane;
                if (c < NTOK) {
                    float e = __expf(vals[cc] - mx);
                    sum += e;
                    u32 o = (u32)(r * 128 + (c & 31) * 4);
                    o ^= (o >> 3) & 0x70;
                    *(u32*)(gp + A_P_OFF + cc * 18432 + o) = cvt_tf32(e);
                }
            }
#pragma unroll
            for (int o2 = 16; o2; o2 >>= 1) sum += __shfl_xor_sync(0xffffffffu, sum, o2);
            if (lane == 0) invp[r] = 1.0f / sum;
        }
        asm volatile("fence.proxy.async.shared::cta;" ::: "memory");
        __syncthreads();

        // ---- PV MMAs: D @col288 (q 0..127), @col320 (q 16..143) ----
        if (tid == 0) {
            ull pd = mk_desc(sb0 + A_P_OFF);
            ull vd = mk_desc(sb0 + A_VT_OFF);
#pragma unroll
            for (int kc = 0; kc < 20; kc++)
                mma_tf32(tmem + 288, pd + (kc >> 2) * 1152 + (kc & 3) * 2,
                                     vd + (kc >> 2) * 256 + (kc & 3) * 2,
                                     IDESC_PV, (u32)(kc > 0));
#pragma unroll
            for (int kc = 0; kc < 20; kc++)
                mma_tf32(tmem + 320, pd + 128 + (kc >> 2) * 1152 + (kc & 3) * 2,
                                     vd + (kc >> 2) * 256 + (kc & 3) * 2,
                                     IDESC_PV, (u32)(kc > 0));
            asm volatile(
                "tcgen05.commit.cta_group::1.mbarrier::arrive::one.shared::cluster.b64 [%0];"
                :: "r"(sb0 + 16) : "memory");
        }
        mbar_wait(sb0 + 16, mph & 1); mph++;
        TMF_AFTER();

        // ---- O epilogue ----
        if (wid < 4) {
            u32 dr[32];
            LDTM32(dr, tmem + 288 + ((u32)wid << 21));
            TMWAIT_LD();
            int q = wid * 32 + lane;
            float iv = invp[q];
            float* ob = ga + (size_t)q * DIM + hb;
#pragma unroll
            for (int c = 0; c < 8; c++) {
                float4 o;
                o.x = __uint_as_float(dr[4 * c + 0]) * iv;
                o.y = __uint_as_float(dr[4 * c + 1]) * iv;
                o.z = __uint_as_float(dr[4 * c + 2]) * iv;
                o.w = __uint_as_float(dr[4 * c + 3]) * iv;
                *(float4*)(ob + 4 * c) = o;
            }
            if (wid == 3) {
                u32 d2[32];
                LDTM32(d2, tmem + 320 + (3u << 21));
                TMWAIT_LD();
                if (lane >= 16) {
                    int q2 = 112 + lane;            // 128..143
                    float iv2 = invp[q2];
                    float* ob2 = ga + (size_t)q2 * DIM + hb;
#pragma unroll
                    for (int c = 0; c < 8; c++) {
                        float4 o;
                        o.x = __uint_as_float(d2[4 * c + 0]) * iv2;
                        o.y = __uint_as_float(d2[4 * c + 1]) * iv2;
                        o.z = __uint_as_float(d2[4 * c + 2]) * iv2;
                        o.w = __uint_as_float(d2[4 * c + 3]) * iv2;
                        *(float4*)(ob2 + 4 * c) = o;
                    }
                }
            }
            TMF_BEFORE();
        }
        __syncthreads();
    }
    if (wid == 0)
        asm volatile("tcgen05.dealloc.cta_group::1.sync.aligned.b32 %0, %1;"
                     :: "r"(tmem), "r"(512u));

#else  // --------- SIMT fallback (never runs when sm_103a cubin loads) ----------
    for (int t = tid; t < HEADS * NTOK; t += 512) {
        int h = t / NTOK, qrow = t - h * NTOK;
        const float* qr = gq + (size_t)qrow * 576 + h * HDIM;
        int iz = qrow / 72, rm = qrow - iz * 72;
        int ih = rm / 12, iw = rm - ih * 12;
        int rp = iz * 828 + ih * 23 + iw + 11;
        float mx = -3.0e38f;
        for (int m = 0; m < NTOK; m++) {
            const float* kr = gq + (size_t)m * 576 + 192 + h * HDIM;
            float s = 0.f;
            for (int d = 0; d < HDIM; d++) s += qr[d] * kr[d];
            int jz = m / 72, rm2 = m - jz * 72;
            int jh = rm2 / 12, jw = rm2 - jh * 12;
            int bi = rp + jz * 1656 + jh * 138 - jw;
            s = s * QSCALE + bias_table[(size_t)bi * (NW * HEADS) + w * HEADS + h]
              + maskb[qrow * NTOK + m];
            mx = fmaxf(mx, s);
        }
        float acc[HDIM];
        for (int d = 0; d < HDIM; d++) acc[d] = 0.f;
        float Z = 0.f;
        for (int m = 0; m < NTOK; m++) {
            const float* kr = gq + (size_t)m * 576 + 192 + h * HDIM;
            float s = 0.f;
            for (int d = 0; d < HDIM; d++) s += qr[d] * kr[d];
            int jz = m / 72, rm2 = m - jz * 72;
            int jh = rm2 / 12, jw = rm2 - jh * 12;
            int bi = rp + jz * 1656 + jh * 138 - jw;
            s = s * QSCALE + bias_table[(size_t)bi * (NW * HEADS) + w * HEADS + h]
              + maskb[qrow * NTOK + m];
            float e = __expf(s - mx);
            Z += e;
            const float* vr = gq + (size_t)m * 576 + 384 + h * HDIM;
            for (int d = 0; d < HDIM; d++) acc[d] += e * vr[d];
        }
        float* ob = ga + (size_t)qrow * DIM + h * HDIM;
        for (int d = 0; d < HDIM; d++) ob[d] = acc[d] / Z;
    }
#endif
}

// ---------------------------------------------------------------------------
extern "C" void kernel_launch(void* const* d_in, const int* in_sizes, int n_in,
                              void* d_out, int out_size)
{
    const float* x    = (const float*)d_in[0];
    const float* mask = (const float*)d_in[1];
    const float* w1   = (const float*)d_in[2];
    const float* b1   = (const float*)d_in[3];
    const float* w2   = (const float*)d_in[4];
    const float* b2   = (const float*)d_in[5];
    const float* bt   = (const float*)d_in[6];
    float* out = (float*)d_out;

    void *qkv_p, *att_p;
    cudaGetSymbolAddress(&qkv_p, g_qkv);
    cudaGetSymbolAddress(&att_p, g_att);
    float* qkv = (float*)qkv_p;
    float* att = (float*)att_p;

    cudaFuncSetAttribute(gemm_tc, cudaFuncAttributeMaxDynamicSharedMemorySize, G_SMEM_SZ);
    cudaFuncSetAttribute(attn_tc, cudaFuncAttributeMaxDynamicSharedMemorySize, ATTN2_SMEM);

    // QKV projection: 241920 x 576 x 192 (tcgen05 tf32)
    gemm_tc<<<MTILES, 256, G_SMEM_SZ>>>(x, w1, b1, qkv, 576);
    // fused attention per (b, w), tcgen05
    attn_tc<<<NW * BATCH, 512, ATTN2_SMEM>>>(qkv, bt, mask, att);
    // output projection: 241920 x 192 x 192 (tcgen05 tf32)
    gemm_tc<<<MTILES, 256, G_SMEM_SZ>>>(att, w2, b2, out, 192);
}

// round 9
// speedup vs baseline: 2.7470x; 1.1193x over previous
#include <cuda_runtime.h>
#include <cuda_bf16.h>
#include <cstdint>

// ---------------------------------------------------------------------------
// EarthAttention3D: B=2, nW=840, N=144, C=192, H=6, d=32
//   All heavy math on tcgen05 kind::tf32 (sm_103a cubin);
//   SIMT fallback bodies for the plain compute_103 ptxas pass.
// ---------------------------------------------------------------------------

typedef unsigned long long ull;
typedef unsigned int u32;

#if defined(__CUDA_ARCH_FEAT_SM103_ALL) || defined(__CUDA_ARCH_FEAT_SM100_ALL) || \
    defined(__CUDA_ARCH_SPECIFIC__)
#define TC_OK 1
#else
#define TC_OK 0
#endif

#define NW     840
#define NTOK   144
#define DIM    192
#define HEADS  6
#define HDIM   32
#define BATCH  2
#define MTOT   (BATCH*NW*NTOK)          // 241920
#define MTILES (MTOT/128)               // 1890
#define TABLE  3312
#define QSCALE 0.17677669529663687f     // 32^-0.5

__device__ float g_qkv[(size_t)MTOT * 576];   // 557 MB scratch
__device__ float g_att[(size_t)MTOT * DIM];   // 186 MB scratch
__device__ float g_wtf[576 * 192];            // prebaked tf32-swizzled W slabs

// ---------------- generic helpers ----------------
__device__ __forceinline__ u32 smem_u32(const void* p) {
    u32 r; asm("{ .reg .u64 t; cvta.to.shared.u64 t, %1; cvt.u32.u64 %0, t; }"
               : "=r"(r) : "l"(p)); return r;
}

#if TC_OK
// ---------------- tcgen05 helpers (arch-specific only) -----------
__device__ __forceinline__ u32 cvt_tf32(float f) {
    u32 r; asm("cvt.rn.tf32.f32 %0, %1;" : "=r"(r) : "f"(f)); return r;
}
__device__ __forceinline__ void mbar_init(u32 mb, u32 cnt) {
    asm volatile("mbarrier.init.shared.b64 [%0], %1;" :: "r"(mb), "r"(cnt) : "memory");
}
__device__ __forceinline__ void mbar_wait(u32 mb, u32 par) {
    asm volatile(
        "{\n\t.reg .pred P;\n\t"
        "W%=:\n\t"
        "mbarrier.try_wait.parity.acquire.cta.shared::cta.b64 P, [%0], %1, 0x989680;\n\t"
        "@P bra D%=;\n\t"
        "bra W%=;\n\t"
        "D%=:\n\t}"
        :: "r"(mb), "r"(par) : "memory");
}
__device__ __forceinline__ ull mk_desc(u32 addr) {   // SW128 K-major, Blackwell v1
    return ((ull)2 << 61) | ((ull)1 << 46) | ((ull)64 << 32) | ((ull)1 << 16)
         | ((addr >> 4) & 0x3FFFull);
}

#define LDTM32(r, ta) \
    asm volatile( \
        "tcgen05.ld.sync.aligned.32x32b.x32.b32 " \
        "{%0, %1, %2, %3, %4, %5, %6, %7, " \
        " %8, %9, %10, %11, %12, %13, %14, %15, " \
        " %16, %17, %18, %19, %20, %21, %22, %23, " \
        " %24, %25, %26, %27, %28, %29, %30, %31}, [%32];" \
        : "=r"((r)[0]),  "=r"((r)[1]),  "=r"((r)[2]),  "=r"((r)[3]), \
          "=r"((r)[4]),  "=r"((r)[5]),  "=r"((r)[6]),  "=r"((r)[7]), \
          "=r"((r)[8]),  "=r"((r)[9]),  "=r"((r)[10]), "=r"((r)[11]), \
          "=r"((r)[12]), "=r"((r)[13]), "=r"((r)[14]), "=r"((r)[15]), \
          "=r"((r)[16]), "=r"((r)[17]), "=r"((r)[18]), "=r"((r)[19]), \
          "=r"((r)[20]), "=r"((r)[21]), "=r"((r)[22]), "=r"((r)[23]), \
          "=r"((r)[24]), "=r"((r)[25]), "=r"((r)[26]), "=r"((r)[27]), \
          "=r"((r)[28]), "=r"((r)[29]), "=r"((r)[30]), "=r"((r)[31]) \
        : "r"(ta))

#define TMWAIT_LD()  asm volatile("tcgen05.wait::ld.sync.aligned;" ::: "memory")
#define TMF_AFTER()  asm volatile("tcgen05.fence::after_thread_sync;" ::: "memory")
#define TMF_BEFORE() asm volatile("tcgen05.fence::before_thread_sync;" ::: "memory")

#define CPA16(dst, src) \
    asm volatile("cp.async.cg.shared.global [%0], [%1], 16;" :: "r"(dst), "l"(src))
#define CPA_COMMIT() asm volatile("cp.async.commit_group;" ::: "memory")
#define CPA_WAIT0()  asm volatile("cp.async.wait_group 0;" ::: "memory")

static constexpr u32 IDESC_G  = (1u<<4)|(2u<<7)|(2u<<10)|((64u/8)<<17)|((128u/16)<<24);
static constexpr u32 IDESC_S  = (1u<<4)|(2u<<7)|(2u<<10)|((144u/8)<<17)|((128u/16)<<24);
static constexpr u32 IDESC_PV = (1u<<4)|(2u<<7)|(2u<<10)|((32u/8)<<17)|((128u/16)<<24);

__device__ __forceinline__ void mma_tf32(u32 dt, ull ad, ull bd, u32 idesc, u32 en) {
    asm volatile(
        "{\n\t.reg .pred p;\n\t"
        "setp.ne.u32 p, %4, 0;\n\t"
        "tcgen05.mma.cta_group::1.kind::tf32 [%0], %1, %2, %3, {%5,%5,%5,%5}, p;\n\t}"
        :: "r"(dt), "l"(ad), "l"(bd), "r"(idesc), "r"(en), "r"(0u) : "memory");
}
#endif  // TC_OK

// ---------------------------------------------------------------------------
// wprep: convert W (Ntot x 192 fp32, NT layout) into tf32 SW128 slab layout.
// Output: per 64-row subtile (49152 B): 3 slabs of 8192 B (64 rows x 32 cols).
// ---------------------------------------------------------------------------
__global__ void wprep(const float* __restrict__ W, float* __restrict__ Wp, int n)
{
    int idx = blockIdx.x * 256 + threadIdx.x;
    if (idx >= n) return;
#if TC_OK
    int row = idx / 48, c4 = idx - row * 48;
    float4 v = *(const float4*)(W + (size_t)row * 192 + c4 * 4);
    uint4 t;
    t.x = cvt_tf32(v.x); t.y = cvt_tf32(v.y);
    t.z = cvt_tf32(v.z); t.w = cvt_tf32(v.w);
    u32 bo = (u32)((row & 63) * 128 + (c4 & 7) * 16);
    bo ^= (bo >> 3) & 0x70;
    char* dst = (char*)Wp + (size_t)(row >> 6) * 49152 + (c4 >> 3) * 8192 + bo;
    *(uint4*)dst = t;
#endif
}

// ---------------------------------------------------------------------------
// GEMM (NT): C[m,n] = A[m,:192] . W[n,:192] + bias[n]   via tcgen05 tf32.
// W comes prebaked (Wp); per-iter refill is 48KB of cp.async.
// ---------------------------------------------------------------------------
#define G_OFF_A   1024u
#define G_OFF_W0  99328u
#define G_OFF_W1  148480u
#define G_SMEM_SZ (197632 + 1024)

#if TC_OK
__device__ __forceinline__ void gtc_epilogue8(u32 tmem, int bufsel, int nsub,
        float* __restrict__ C, const float* __restrict__ bias, int Ntot,
        int bm, int wid, int lane) {
    const int sp = wid & 3, ch = wid >> 2;
    u32 dt = tmem + (u32)(bufsel * 64 + ch * 32) + ((u32)sp << 21);
    u32 dr[32];
    TMF_AFTER();
    LDTM32(dr, dt);
    TMWAIT_LD();
    TMF_BEFORE();
    int m = bm + sp * 32 + lane;
    float* crow = C + (size_t)m * Ntot + nsub * 64 + ch * 32;
    const float4* b4 = (const float4*)(bias + nsub * 64 + ch * 32);
#pragma unroll
    for (int c = 0; c < 8; c++) {
        float4 bb = b4[c];
        float4 o;
        o.x = __uint_as_float(dr[4 * c + 0]) + bb.x;
        o.y = __uint_as_float(dr[4 * c + 1]) + bb.y;
        o.z = __uint_as_float(dr[4 * c + 2]) + bb.z;
        o.w = __uint_as_float(dr[4 * c + 3]) + bb.w;
        *(float4*)(crow + 4 * c) = o;
    }
}
#endif  // TC_OK

__global__ __launch_bounds__(256, 1) void gemm_tc(
    const float* __restrict__ A, const float* __restrict__ W,
    const float* __restrict__ Wp, const float* __restrict__ bias,
    float* __restrict__ C, int Ntot)
{
    extern __shared__ char gsm_raw[];
    u32 sb_raw = smem_u32(gsm_raw);
    u32 sb0 = (sb_raw + 1023u) & ~1023u;
    char* gp = gsm_raw + (sb0 - sb_raw);

    const int tid = threadIdx.x;
    const int bm = blockIdx.x * 128;

#if TC_OK
    const int wid = tid >> 5, lane = tid & 31;
    const int niter = Ntot >> 6;

    if (wid == 0) {
        asm volatile("tcgen05.alloc.cta_group::1.sync.aligned.shared::cta.b32 [%0], %1;"
                     :: "r"(sb0), "r"(128u) : "memory");
        asm volatile("tcgen05.relinquish_alloc_permit.cta_group::1.sync.aligned;");
    }
    if (tid == 0) { mbar_init(sb0 + 16, 1); mbar_init(sb0 + 24, 1); }

    // kick W0 copy (async) first so it overlaps the A conversion below
    {
        const char* wsrc = (const char*)Wp;
#pragma unroll
        for (int j = 0; j < 12; j++) {
            int o = (tid + j * 256) * 16;
            CPA16(sb0 + G_OFF_W0 + (u32)o, wsrc + o);
        }
        CPA_COMMIT();
    }

    // A tile (128 x 192): LDG + tf32 round + SW128 STS
    const float* Ab = A + (size_t)bm * 192;
#pragma unroll
    for (int j = 0; j < 24; j++) {
        int idx = tid + j * 256;
        int row = idx / 48, c4 = idx - row * 48;
        float4 v = *(const float4*)(Ab + row * 192 + c4 * 4);
        uint4 t;
        t.x = cvt_tf32(v.x); t.y = cvt_tf32(v.y);
        t.z = cvt_tf32(v.z); t.w = cvt_tf32(v.w);
        u32 bo = (u32)(row * 128 + (c4 & 7) * 16);
        bo ^= (bo >> 3) & 0x70;
        *(uint4*)(gp + G_OFF_A + (c4 >> 3) * 16384 + bo) = t;
    }
    CPA_WAIT0();
    asm volatile("fence.proxy.async.shared::cta;" ::: "memory");
    __syncthreads();

    u32 tmem;
    asm("ld.shared.b32 %0, [%1];" : "=r"(tmem) : "r"(sb0));

    const ull descA = mk_desc(sb0 + G_OFF_A);
    u32 ph0 = 0, ph1 = 0;

    for (int it = 0; it < niter; it++) {
        const int buf = it & 1;
        if (it > 0) {              // W(it) copy (issued last iter) must be visible
            CPA_WAIT0();
            asm volatile("fence.proxy.async.shared::cta;" ::: "memory");
            __syncthreads();
        }
        if (tid == 0) {
            ull descW = mk_desc(sb0 + (buf ? G_OFF_W1 : G_OFF_W0));
            u32 dtm = tmem + buf * 64;
#pragma unroll
            for (int k = 0; k < 24; k++)
                mma_tf32(dtm, descA + (k >> 2) * 1024 + (k & 3) * 2,
                              descW + (k >> 2) * 512 + (k & 3) * 2, IDESC_G, (u32)(k > 0));
            asm volatile(
                "tcgen05.commit.cta_group::1.mbarrier::arrive::one.shared::cluster.b64 [%0];"
                :: "r"(sb0 + 16 + buf * 8) : "memory");
        }
        if (it > 0) {
            const int pb = buf ^ 1;
            if (pb == 0) { mbar_wait(sb0 + 16, ph0); ph0 ^= 1; }
            else         { mbar_wait(sb0 + 24, ph1); ph1 ^= 1; }
            // buf^1 now free: start W(it+1) copy, then overlap epilogue with it
            if (it + 1 < niter) {
                const char* wsrc = (const char*)Wp + (size_t)(it + 1) * 49152;
                u32 wdst = sb0 + (buf ? G_OFF_W0 : G_OFF_W1);
#pragma unroll
                for (int j = 0; j < 12; j++) {
                    int o = (tid + j * 256) * 16;
                    CPA16(wdst + (u32)o, wsrc + o);
                }
                CPA_COMMIT();
            }
            gtc_epilogue8(tmem, pb, it - 1, C, bias, Ntot, bm, wid, lane);
        } else if (niter > 1) {
            // prologue for W1 (no MMA has used buffer 1 yet)
            const char* wsrc = (const char*)Wp + 49152;
#pragma unroll
            for (int j = 0; j < 12; j++) {
                int o = (tid + j * 256) * 16;
                CPA16(sb0 + G_OFF_W1 + (u32)o, wsrc + o);
            }
            CPA_COMMIT();
        }
    }
    {
        const int lb = (niter - 1) & 1;
        if (lb == 0) mbar_wait(sb0 + 16, ph0);
        else         mbar_wait(sb0 + 24, ph1);
        gtc_epilogue8(tmem, lb, niter - 1, C, bias, Ntot, bm, wid, lane);
    }
    __syncthreads();
    if (wid == 0)
        asm volatile("tcgen05.dealloc.cta_group::1.sync.aligned.b32 %0, %1;"
                     :: "r"(tmem), "r"(128u));

#else  // --------- SIMT fp32 fallback ----------
    float* As = (float*)gp;
    const float* Ab = A + (size_t)bm * 192;
    for (int i = tid; i < 128 * 48; i += 256)
        ((float4*)As)[i] = ((const float4*)Ab)[i];
    __syncthreads();
    for (int idx = tid; idx < 128 * Ntot; idx += 256) {
        int col = idx >> 7, row = idx & 127;
        const float4* ar = (const float4*)(As + row * 192);
        const float4* wr = (const float4*)(W + (size_t)col * 192);
        float s = 0.f;
#pragma unroll 8
        for (int k = 0; k < 48; k++) {
            float4 a = ar[k], w = wr[k];
            s += a.x * w.x + a.y * w.y + a.z * w.z + a.w * w.w;
        }
        C[(size_t)(bm + row) * Ntot + col] = s + bias[col];
    }
#endif
}

// ---------------------------------------------------------------------------
// tcgen05 attention: one CTA per (b,w), 512 threads, 6 heads sequential.
// S = q k^T (M=query 144 via 2x M128 MMAs, N=144 keys, K=32) -> LDTM gives
// each thread a query row -> register softmax (max-free; bias arithmetic +
// LDS imm-offset, mask row-contiguous LDG) -> STS.64 into P slabs ->
// PV (18 K-chunks) -> O epilogue scales by in-register 1/Z.
// SMEM: P 5x18432 @1024 (q stage slab0, k slab1) | VT 5x4096 | bias cache 6H
// ---------------------------------------------------------------------------
#define A_P_OFF   1024u
#define A_VT_OFF  93184u
#define A_BC_OFF  113664u
#define ATTN2_SMEM (193152 + 2048)

#if TC_OK
__device__ __forceinline__ int cp6(int c) {   // column part of bias idx, x6
    int jz = c / 72, r = c - jz * 72;
    int jh = r / 12, jw = r - jh * 12;
    return (jz * 1656 + jh * 138 - jw) * 6;
}
#endif

__global__ __launch_bounds__(512, 1) void attn_tc(
    const float* __restrict__ qkv, const float* __restrict__ bias_table,
    const float* __restrict__ mask, float* __restrict__ outp)
{
    extern __shared__ char asm_raw[];
    u32 sb_raw = smem_u32(asm_raw);
    u32 sb0 = (sb_raw + 1023u) & ~1023u;
    char* gp = asm_raw + (sb0 - sb_raw);

    const int tid = threadIdx.x;
    const int w = blockIdx.x >> 1;
    const int b = blockIdx.x & 1;
    const float* gq = qkv + (size_t)(b * NW + w) * NTOK * 576;
    const float* maskb = mask + (size_t)b * NTOK * NTOK;
    float* ga = outp + (size_t)(b * NW + w) * NTOK * DIM;

#if TC_OK
    const int wid = tid >> 5, lane = tid & 31;

    if (wid == 0) {
        asm volatile("tcgen05.alloc.cta_group::1.sync.aligned.shared::cta.b32 [%0], %1;"
                     :: "r"(sb0), "r"(512u) : "memory");
        asm volatile("tcgen05.relinquish_alloc_permit.cta_group::1.sync.aligned;");
    }
    if (tid == 0) mbar_init(sb0 + 16, 1);

    // ---- bias cache for all 6 heads: bc[i*6+h] ----
    {
        float* bc = (float*)(gp + A_BC_OFF);
        for (int idx = tid; idx < TABLE * 6; idx += 512) {
            int i = idx / 6, hh = idx - i * 6;
            bc[idx] = bias_table[(size_t)i * (NW * HEADS) + w * HEADS + hh];
        }
    }

    // softmax/epilogue role: warps 0-3 -> D1 queries 0..127; warp 7 -> D2 tail
    const bool is_smx = (wid < 4) || (wid == 7);
    const int qrow = (wid < 4) ? wid * 32 + lane : 112 + lane;
    const bool act = (wid < 4) || (wid == 7 && lane >= 16);
    const int dbase = (wid < 4) ? 0 : 144;
    const u32 lofs = (u32)(((wid < 4) ? wid : 3) << 21);
    int rp6;
    {
        int iz = qrow / 72, rm = qrow - iz * 72;
        int ih = rm / 12, iw = rm - ih * 12;
        rp6 = (iz * 828 + ih * 23 + iw + 11) * 6;
    }
    const float* mrow = maskb + qrow * NTOK;
    __syncthreads();

    u32 tmem;
    asm("ld.shared.b32 %0, [%1];" : "=r"(tmem) : "r"(sb0));
    const float* bcf = (const float*)(gp + A_BC_OFF);
    u32 mph = 0;

    for (int h = 0; h < HEADS; h++) {
        const int hb = h * HDIM;
        // ---- stage q (slab0, scaled) and k (slab1) ----
        for (int idx = tid; idx < 1152; idx += 512) {
            int row = idx >> 3, c4 = idx & 7;
            float4 v = *(const float4*)(gq + (size_t)row * 576 + hb + c4 * 4);
            uint4 t;
            t.x = cvt_tf32(v.x * QSCALE); t.y = cvt_tf32(v.y * QSCALE);
            t.z = cvt_tf32(v.z * QSCALE); t.w = cvt_tf32(v.w * QSCALE);
            u32 bo = (u32)(row * 128 + c4 * 16);
            bo ^= (bo >> 3) & 0x70;
            *(uint4*)(gp + A_P_OFF + bo) = t;
        }
        for (int idx = tid; idx < 1152; idx += 512) {
            int row = idx >> 3, c4 = idx & 7;
            float4 v = *(const float4*)(gq + (size_t)row * 576 + 192 + hb + c4 * 4);
            uint4 t;
            t.x = cvt_tf32(v.x); t.y = cvt_tf32(v.y);
            t.z = cvt_tf32(v.z); t.w = cvt_tf32(v.w);
            u32 bo = (u32)(row * 128 + c4 * 16);
            bo ^= (bo >> 3) & 0x70;
            *(uint4*)(gp + A_P_OFF + 18432 + bo) = t;
        }
        asm volatile("fence.proxy.async.shared::cta;" ::: "memory");
        __syncthreads();

        // ---- issue S MMAs: D1 (q 0..127) @col0, D2 (q 16..143) @col144 ----
        if (tid == 0) {
            ull qd = mk_desc(sb0 + A_P_OFF);
            ull kd = mk_desc(sb0 + A_P_OFF + 18432);
#pragma unroll
            for (int c = 0; c < 4; c++)
                mma_tf32(tmem, qd + c * 2, kd + c * 2, IDESC_S, (u32)(c > 0));
#pragma unroll
            for (int c = 0; c < 4; c++)
                mma_tf32(tmem + 144, qd + 128 + c * 2, kd + c * 2, IDESC_S, (u32)(c > 0));
            asm volatile(
                "tcgen05.commit.cta_group::1.mbarrier::arrive::one.shared::cluster.b64 [%0];"
                :: "r"(sb0 + 16) : "memory");
        }

        // ---- stage V^T (overlaps the S MMA) ----
        for (int idx = tid; idx < 1152; idx += 512) {
            int m = idx % NTOK, d4 = idx / NTOK;       // d4 in 0..7
            float4 v = *(const float4*)(gq + (size_t)m * 576 + 384 + hb + d4 * 4);
            char* slab = gp + A_VT_OFF + (m >> 5) * 4096;
            u32 colb = (u32)((m & 31) * 4);
#pragma unroll
            for (int j = 0; j < 4; j++) {
                u32 bo = (u32)((d4 * 4 + j) * 128) + colb;
                bo ^= (bo >> 3) & 0x70;
                float val = j == 0 ? v.x : (j == 1 ? v.y : (j == 2 ? v.z : v.w));
                *(u32*)(slab + bo) = cvt_tf32(val);
            }
        }

        mbar_wait(sb0 + 16, mph & 1); mph++;

        // ---- register softmax + P store ----
        float inv = 0.f;
        if (is_smx) {
            TMF_AFTER();
            const float* brp = bcf + rp6 + h;
            const u32 rowb = (u32)(qrow * 128);
            float sum = 0.f;
#pragma unroll
            for (int cc = 0; cc < 5; cc++) {
                u32 dr[32];
                LDTM32(dr, tmem + dbase + cc * 32 + lofs);
                TMWAIT_LD();
                if (act) {
                    char* ps = gp + A_P_OFF + cc * 18432;
#pragma unroll
                    for (int j0 = 0; j0 < 32; j0 += 4) {
                        const int c = cc * 32 + j0;
                        if (c < NTOK) {
                            float4 mv = *(const float4*)(mrow + c);
                            float e0 = __expf(__uint_as_float(dr[j0+0]) + brp[cp6(c+0)] + mv.x);
                            float e1 = __expf(__uint_as_float(dr[j0+1]) + brp[cp6(c+1)] + mv.y);
                            float e2 = __expf(__uint_as_float(dr[j0+2]) + brp[cp6(c+2)] + mv.z);
                            float e3 = __expf(__uint_as_float(dr[j0+3]) + brp[cp6(c+3)] + mv.w);
                            sum += (e0 + e1) + (e2 + e3);
                            u32 t0 = cvt_tf32(e0), t1 = cvt_tf32(e1);
                            u32 t2 = cvt_tf32(e2), t3 = cvt_tf32(e3);
                            u32 o = rowb + (u32)((c & 31) * 4);
                            o ^= (o >> 3) & 0x70;
                            asm volatile("st.shared.v2.b32 [%0], {%1,%2};"
                                         :: "r"(smem_u32(ps) + o), "r"(t0), "r"(t1));
                            u32 o2 = rowb + (u32)(((c + 2) & 31) * 4);
                            o2 ^= (o2 >> 3) & 0x70;
                            asm volatile("st.shared.v2.b32 [%0], {%1,%2};"
                                         :: "r"(smem_u32(ps) + o2), "r"(t2), "r"(t3));
                        }
                    }
                }
            }
            TMF_BEFORE();
            inv = 1.0f / sum;
        }
        asm volatile("fence.proxy.async.shared::cta;" ::: "memory");
        __syncthreads();

        // ---- PV MMAs: O-D1 @col288, O-D2 @col320 (18 K-chunks, K=144) ----
        if (tid == 0) {
            ull pd = mk_desc(sb0 + A_P_OFF);
            ull vd = mk_desc(sb0 + A_VT_OFF);
#pragma unroll
            for (int kc = 0; kc < 18; kc++)
                mma_tf32(tmem + 288, pd + (kc >> 2) * 1152 + (kc & 3) * 2,
                                     vd + (kc >> 2) * 256 + (kc & 3) * 2,
                                     IDESC_PV, (u32)(kc > 0));
#pragma unroll
            for (int kc = 0; kc < 18; kc++)
                mma_tf32(tmem + 320, pd + 128 + (kc >> 2) * 1152 + (kc & 3) * 2,
                                     vd + (kc >> 2) * 256 + (kc & 3) * 2,
                                     IDESC_PV, (u32)(kc > 0));
            asm volatile(
                "tcgen05.commit.cta_group::1.mbarrier::arrive::one.shared::cluster.b64 [%0];"
                :: "r"(sb0 + 16) : "memory");
        }
        mbar_wait(sb0 + 16, mph & 1); mph++;

        // ---- O epilogue (same thread<->query mapping; inv in register) ----
        if (is_smx) {
            TMF_AFTER();
            u32 dr[32];
            LDTM32(dr, tmem + ((wid < 4) ? 288u : 320u) + lofs);
            TMWAIT_LD();
            TMF_BEFORE();
            if (act) {
                float* ob = ga + (size_t)qrow * DIM + hb;
#pragma unroll
                for (int c = 0; c < 8; c++) {
                    float4 o;
                    o.x = __uint_as_float(dr[4 * c + 0]) * inv;
                    o.y = __uint_as_float(dr[4 * c + 1]) * inv;
                    o.z = __uint_as_float(dr[4 * c + 2]) * inv;
                    o.w = __uint_as_float(dr[4 * c + 3]) * inv;
                    *(float4*)(ob + 4 * c) = o;
                }
            }
        }
        __syncthreads();
    }
    if (wid == 0)
        asm volatile("tcgen05.dealloc.cta_group::1.sync.aligned.b32 %0, %1;"
                     :: "r"(tmem), "r"(512u));

#else  // --------- SIMT fallback (never runs when sm_103a cubin loads) ----------
    for (int t = tid; t < HEADS * NTOK; t += 512) {
        int h = t / NTOK, qrow = t - h * NTOK;
        const float* qr = gq + (size_t)qrow * 576 + h * HDIM;
        int iz = qrow / 72, rm = qrow - iz * 72;
        int ih = rm / 12, iw = rm - ih * 12;
        int rp = iz * 828 + ih * 23 + iw + 11;
        float mx = -3.0e38f;
        for (int m = 0; m < NTOK; m++) {
            const float* kr = gq + (size_t)m * 576 + 192 + h * HDIM;
            float s = 0.f;
            for (int d = 0; d < HDIM; d++) s += qr[d] * kr[d];
            int jz = m / 72, rm2 = m - jz * 72;
            int jh = rm2 / 12, jw = rm2 - jh * 12;
            int bi = rp + jz * 1656 + jh * 138 - jw;
            s = s * QSCALE + bias_table[(size_t)bi * (NW * HEADS) + w * HEADS + h]
              + maskb[qrow * NTOK + m];
            mx = fmaxf(mx, s);
        }
        float acc[HDIM];
        for (int d = 0; d < HDIM; d++) acc[d] = 0.f;
        float Z = 0.f;
        for (int m = 0; m < NTOK; m++) {
            const float* kr = gq + (size_t)m * 576 + 192 + h * HDIM;
            float s = 0.f;
            for (int d = 0; d < HDIM; d++) s += qr[d] * kr[d];
            int jz = m / 72, rm2 = m - jz * 72;
            int jh = rm2 / 12, jw = rm2 - jh * 12;
            int bi = rp + jz * 1656 + jh * 138 - jw;
            s = s * QSCALE + bias_table[(size_t)bi * (NW * HEADS) + w * HEADS + h]
              + maskb[qrow * NTOK + m];
            float e = __expf(s - mx);
            Z += e;
            const float* vr = gq + (size_t)m * 576 + 384 + h * HDIM;
            for (int d = 0; d < HDIM; d++) acc[d] += e * vr[d];
        }
        float* ob = ga + (size_t)qrow * DIM + h * HDIM;
        for (int d = 0; d < HDIM; d++) ob[d] = acc[d] / Z;
    }
#endif
}

// ---------------------------------------------------------------------------
extern "C" void kernel_launch(void* const* d_in, const int* in_sizes, int n_in,
                              void* d_out, int out_size)
{
    const float* x    = (const float*)d_in[0];
    const float* mask = (const float*)d_in[1];
    const float* w1   = (const float*)d_in[2];
    const float* b1   = (const float*)d_in[3];
    const float* w2   = (const float*)d_in[4];
    const float* b2   = (const float*)d_in[5];
    const float* bt   = (const float*)d_in[6];
    float* out = (float*)d_out;

    void *qkv_p, *att_p, *wtf_p;
    cudaGetSymbolAddress(&qkv_p, g_qkv);
    cudaGetSymbolAddress(&att_p, g_att);
    cudaGetSymbolAddress(&wtf_p, g_wtf);
    float* qkv = (float*)qkv_p;
    float* att = (float*)att_p;
    float* wtf = (float*)wtf_p;

    cudaFuncSetAttribute(gemm_tc, cudaFuncAttributeMaxDynamicSharedMemorySize, G_SMEM_SZ);
    cudaFuncSetAttribute(attn_tc, cudaFuncAttributeMaxDynamicSharedMemorySize, ATTN2_SMEM);

    // QKV projection: 241920 x 576 x 192
    wprep<<<(576 * 48 + 255) / 256, 256>>>(w1, wtf, 576 * 48);
    gemm_tc<<<MTILES, 256, G_SMEM_SZ>>>(x, w1, wtf, b1, qkv, 576);
    // fused attention per (b, w)
    attn_tc<<<NW * BATCH, 512, ATTN2_SMEM>>>(qkv, bt, mask, att);
    // output projection: 241920 x 192 x 192
    wprep<<<(192 * 48 + 255) / 256, 256>>>(w2, wtf, 192 * 48);
    gemm_tc<<<MTILES, 256, G_SMEM_SZ>>>(att, w2, wtf, b2, out, 192);
}

// round 13
// speedup vs baseline: 3.0125x; 1.0967x over previous
#include <cuda_runtime.h>
#include <cuda_bf16.h>
#include <cstdint>

// ---------------------------------------------------------------------------
// EarthAttention3D: B=2, nW=840, N=144, C=192, H=6, d=32
//   All heavy math on tcgen05 kind::tf32 (sm_103a cubin);
//   SIMT fallback bodies for the plain compute_103 ptxas pass.
// ---------------------------------------------------------------------------

typedef unsigned long long ull;
typedef unsigned int u32;

#if defined(__CUDA_ARCH_FEAT_SM103_ALL) || defined(__CUDA_ARCH_FEAT_SM100_ALL) || \
    defined(__CUDA_ARCH_SPECIFIC__)
#define TC_OK 1
#else
#define TC_OK 0
#endif

#define NW     840
#define NTOK   144
#define DIM    192
#define HEADS  6
#define HDIM   32
#define BATCH  2
#define MTOT   (BATCH*NW*NTOK)          // 241920
#define MTILES (MTOT/128)               // 1890
#define TABLE  3312
#define QSCALE 0.17677669529663687f     // 32^-0.5

__device__ float g_qkv[(size_t)MTOT * 576];   // 557 MB scratch (tf32-rounded)
__device__ float g_att[(size_t)MTOT * DIM];   // 186 MB scratch (tf32-rounded)
__device__ float g_wtf[576 * 192];            // prebaked tf32-swizzled W slabs

// ---------------- generic helpers ----------------
__device__ __forceinline__ u32 smem_u32(const void* p) {
    u32 r; asm("{ .reg .u64 t; cvta.to.shared.u64 t, %1; cvt.u32.u64 %0, t; }"
               : "=r"(r) : "l"(p)); return r;
}

#if TC_OK
// ---------------- tcgen05 helpers (arch-specific only) -----------
__device__ __forceinline__ u32 cvt_tf32(float f) {
    u32 r; asm("cvt.rn.tf32.f32 %0, %1;" : "=r"(r) : "f"(f)); return r;
}
__device__ __forceinline__ void mbar_init(u32 mb, u32 cnt) {
    asm volatile("mbarrier.init.shared.b64 [%0], %1;" :: "r"(mb), "r"(cnt) : "memory");
}
__device__ __forceinline__ void mbar_wait(u32 mb, u32 par) {
    asm volatile(
        "{\n\t.reg .pred P;\n\t"
        "W%=:\n\t"
        "mbarrier.try_wait.parity.acquire.cta.shared::cta.b64 P, [%0], %1, 0x989680;\n\t"
        "@P bra D%=;\n\t"
        "bra W%=;\n\t"
        "D%=:\n\t}"
        :: "r"(mb), "r"(par) : "memory");
}
__device__ __forceinline__ ull mk_desc(u32 addr) {   // SW128 K-major, Blackwell v1
    return ((ull)2 << 61) | ((ull)1 << 46) | ((ull)64 << 32) | ((ull)1 << 16)
         | ((addr >> 4) & 0x3FFFull);
}

#define LDTM32(r, ta) \
    asm volatile( \
        "tcgen05.ld.sync.aligned.32x32b.x32.b32 " \
        "{%0, %1, %2, %3, %4, %5, %6, %7, " \
        " %8, %9, %10, %11, %12, %13, %14, %15, " \
        " %16, %17, %18, %19, %20, %21, %22, %23, " \
        " %24, %25, %26, %27, %28, %29, %30, %31}, [%32];" \
        : "=r"((r)[0]),  "=r"((r)[1]),  "=r"((r)[2]),  "=r"((r)[3]), \
          "=r"((r)[4]),  "=r"((r)[5]),  "=r"((r)[6]),  "=r"((r)[7]), \
          "=r"((r)[8]),  "=r"((r)[9]),  "=r"((r)[10]), "=r"((r)[11]), \
          "=r"((r)[12]), "=r"((r)[13]), "=r"((r)[14]), "=r"((r)[15]), \
          "=r"((r)[16]), "=r"((r)[17]), "=r"((r)[18]), "=r"((r)[19]), \
          "=r"((r)[20]), "=r"((r)[21]), "=r"((r)[22]), "=r"((r)[23]), \
          "=r"((r)[24]), "=r"((r)[25]), "=r"((r)[26]), "=r"((r)[27]), \
          "=r"((r)[28]), "=r"((r)[29]), "=r"((r)[30]), "=r"((r)[31]) \
        : "r"(ta))

#define TMWAIT_LD()  asm volatile("tcgen05.wait::ld.sync.aligned;" ::: "memory")
#define TMF_AFTER()  asm volatile("tcgen05.fence::after_thread_sync;" ::: "memory")
#define TMF_BEFORE() asm volatile("tcgen05.fence::before_thread_sync;" ::: "memory")

#define CPA16(dst, src) \
    asm volatile("cp.async.cg.shared.global [%0], [%1], 16;" :: "r"(dst), "l"(src))
#define CPA_COMMIT() asm volatile("cp.async.commit_group;" ::: "memory")
#define CPA_WAIT0()  asm volatile("cp.async.wait_all;" ::: "memory")

static constexpr u32 IDESC_G  = (1u<<4)|(2u<<7)|(2u<<10)|((64u/8)<<17)|((128u/16)<<24);
static constexpr u32 IDESC_S  = (1u<<4)|(2u<<7)|(2u<<10)|((144u/8)<<17)|((128u/16)<<24);
static constexpr u32 IDESC_PV = (1u<<4)|(2u<<7)|(2u<<10)|((32u/8)<<17)|((128u/16)<<24);

__device__ __forceinline__ void mma_tf32(u32 dt, ull ad, ull bd, u32 idesc, u32 en) {
    asm volatile(
        "{\n\t.reg .pred p;\n\t"
        "setp.ne.u32 p, %4, 0;\n\t"
        "tcgen05.mma.cta_group::1.kind::tf32 [%0], %1, %2, %3, {%5,%5,%5,%5}, p;\n\t}"
        :: "r"(dt), "l"(ad), "l"(bd), "r"(idesc), "r"(en), "r"(0u) : "memory");
}
#endif  // TC_OK

// ---------------------------------------------------------------------------
// wprep: convert W (Ntot x 192 fp32, NT layout) into tf32 SW128 slab layout.
// ---------------------------------------------------------------------------
__global__ void wprep(const float* __restrict__ W, float* __restrict__ Wp, int n)
{
    int idx = blockIdx.x * 256 + threadIdx.x;
    if (idx >= n) return;
#if TC_OK
    int row = idx / 48, c4 = idx - row * 48;
    float4 v = *(const float4*)(W + (size_t)row * 192 + c4 * 4);
    uint4 t;
    t.x = cvt_tf32(v.x); t.y = cvt_tf32(v.y);
    t.z = cvt_tf32(v.z); t.w = cvt_tf32(v.w);
    u32 bo = (u32)((row & 63) * 128 + (c4 & 7) * 16);
    bo ^= (bo >> 3) & 0x70;
    char* dst = (char*)Wp + (size_t)(row >> 6) * 49152 + (c4 >> 3) * 8192 + bo;
    *(uint4*)dst = t;
#endif
}

// ---------------------------------------------------------------------------
// GEMM (NT): C[m,n] = A[m,:192] . W[n,:192] + bias[n]   via tcgen05 tf32.
// W prebaked (Wp, cp.async); A via cp.async when a_pre (data tf32-rounded)
// else LDG+cvt+STS. rnd_out rounds C to tf32 (for qkv / attn scratch).
// ---------------------------------------------------------------------------
#define G_OFF_A   1024u
#define G_OFF_W0  99328u
#define G_OFF_W1  148480u
#define G_SMEM_SZ (197632 + 1024)

#if TC_OK
__device__ __forceinline__ void gtc_epilogue8(u32 tmem, int bufsel, int nsub,
        float* __restrict__ C, const float* __restrict__ bias, int Ntot,
        int bm, int wid, int lane, int rnd_out) {
    const int sp = wid & 3, ch = wid >> 2;
    u32 dt = tmem + (u32)(bufsel * 64 + ch * 32) + ((u32)sp << 21);
    u32 dr[32];
    TMF_AFTER();
    LDTM32(dr, dt);
    TMWAIT_LD();
    TMF_BEFORE();
    int m = bm + sp * 32 + lane;
    float* crow = C + (size_t)m * Ntot + nsub * 64 + ch * 32;
    const float4* b4 = (const float4*)(bias + nsub * 64 + ch * 32);
#pragma unroll
    for (int c = 0; c < 8; c++) {
        float4 bb = b4[c];
        float4 o;
        o.x = __uint_as_float(dr[4 * c + 0]) + bb.x;
        o.y = __uint_as_float(dr[4 * c + 1]) + bb.y;
        o.z = __uint_as_float(dr[4 * c + 2]) + bb.z;
        o.w = __uint_as_float(dr[4 * c + 3]) + bb.w;
        if (rnd_out) {
            o.x = __uint_as_float(cvt_tf32(o.x));
            o.y = __uint_as_float(cvt_tf32(o.y));
            o.z = __uint_as_float(cvt_tf32(o.z));
            o.w = __uint_as_float(cvt_tf32(o.w));
        }
        *(float4*)(crow + 4 * c) = o;
    }
}
#endif  // TC_OK

__global__ __launch_bounds__(256, 1) void gemm_tc(
    const float* __restrict__ A, const float* __restrict__ W,
    const float* __restrict__ Wp, const float* __restrict__ bias,
    float* __restrict__ C, int Ntot, int rnd_out, int a_pre)
{
    extern __shared__ char gsm_raw[];
    u32 sb_raw = smem_u32(gsm_raw);
    u32 sb0 = (sb_raw + 1023u) & ~1023u;
    char* gp = gsm_raw + (sb0 - sb_raw);

    const int tid = threadIdx.x;
    const int bm = blockIdx.x * 128;

#if TC_OK
    const int wid = tid >> 5, lane = tid & 31;
    const int niter = Ntot >> 6;

    if (wid == 0) {
        asm volatile("tcgen05.alloc.cta_group::1.sync.aligned.shared::cta.b32 [%0], %1;"
                     :: "r"(sb0), "r"(128u) : "memory");
        asm volatile("tcgen05.relinquish_alloc_permit.cta_group::1.sync.aligned;");
    }
    if (tid == 0) { mbar_init(sb0 + 16, 1); mbar_init(sb0 + 24, 1); }

    // kick W0 copy (async) first
    {
        const char* wsrc = (const char*)Wp;
#pragma unroll
        for (int j = 0; j < 12; j++) {
            int o = (tid + j * 256) * 16;
            CPA16(sb0 + G_OFF_W0 + (u32)o, wsrc + o);
        }
        CPA_COMMIT();
    }

    // A tile (128 x 192)
    const float* Ab = A + (size_t)bm * 192;
    if (a_pre) {   // data already tf32-rounded: raw cp.async with swizzled dst
#pragma unroll
        for (int j = 0; j < 24; j++) {
            int idx = tid + j * 256;
            int row = idx / 48, c4 = idx - row * 48;
            u32 bo = (u32)(row * 128 + (c4 & 7) * 16);
            bo ^= (bo >> 3) & 0x70;
            CPA16(sb0 + G_OFF_A + (u32)((c4 >> 3) * 16384) + bo,
                  (const char*)Ab + (size_t)row * 768 + c4 * 16);
        }
        CPA_COMMIT();
    } else {
#pragma unroll
        for (int j = 0; j < 24; j++) {
            int idx = tid + j * 256;
            int row = idx / 48, c4 = idx - row * 48;
            float4 v = *(const float4*)(Ab + row * 192 + c4 * 4);
            uint4 t;
            t.x = cvt_tf32(v.x); t.y = cvt_tf32(v.y);
            t.z = cvt_tf32(v.z); t.w = cvt_tf32(v.w);
            u32 bo = (u32)(row * 128 + (c4 & 7) * 16);
            bo ^= (bo >> 3) & 0x70;
            *(uint4*)(gp + G_OFF_A + (c4 >> 3) * 16384 + bo) = t;
        }
    }
    CPA_WAIT0();
    asm volatile("fence.proxy.async.shared::cta;" ::: "memory");
    __syncthreads();

    u32 tmem;
    asm("ld.shared.b32 %0, [%1];" : "=r"(tmem) : "r"(sb0));

    const ull descA = mk_desc(sb0 + G_OFF_A);
    u32 ph0 = 0, ph1 = 0;

    for (int it = 0; it < niter; it++) {
        const int buf = it & 1;
        if (it > 0) {
            CPA_WAIT0();
            asm volatile("fence.proxy.async.shared::cta;" ::: "memory");
            __syncthreads();
        }
        if (tid == 0) {
            ull descW = mk_desc(sb0 + (buf ? G_OFF_W1 : G_OFF_W0));
            u32 dtm = tmem + buf * 64;
#pragma unroll
            for (int k = 0; k < 24; k++)
                mma_tf32(dtm, descA + (k >> 2) * 1024 + (k & 3) * 2,
                              descW + (k >> 2) * 512 + (k & 3) * 2, IDESC_G, (u32)(k > 0));
            asm volatile(
                "tcgen05.commit.cta_group::1.mbarrier::arrive::one.shared::cluster.b64 [%0];"
                :: "r"(sb0 + 16 + buf * 8) : "memory");
        }
        if (it > 0) {
            const int pb = buf ^ 1;
            if (pb == 0) { mbar_wait(sb0 + 16, ph0); ph0 ^= 1; }
            else         { mbar_wait(sb0 + 24, ph1); ph1 ^= 1; }
            if (it + 1 < niter) {
                const char* wsrc = (const char*)Wp + (size_t)(it + 1) * 49152;
                u32 wdst = sb0 + (buf ? G_OFF_W0 : G_OFF_W1);
#pragma unroll
                for (int j = 0; j < 12; j++) {
                    int o = (tid + j * 256) * 16;
                    CPA16(wdst + (u32)o, wsrc + o);
                }
                CPA_COMMIT();
            }
            gtc_epilogue8(tmem, pb, it - 1, C, bias, Ntot, bm, wid, lane, rnd_out);
        } else if (niter > 1) {
            const char* wsrc = (const char*)Wp + 49152;
#pragma unroll
            for (int j = 0; j < 12; j++) {
                int o = (tid + j * 256) * 16;
                CPA16(sb0 + G_OFF_W1 + (u32)o, wsrc + o);
            }
            CPA_COMMIT();
        }
    }
    {
        const int lb = (niter - 1) & 1;
        if (lb == 0) mbar_wait(sb0 + 16, ph0);
        else         mbar_wait(sb0 + 24, ph1);
        gtc_epilogue8(tmem, lb, niter - 1, C, bias, Ntot, bm, wid, lane, rnd_out);
    }
    __syncthreads();
    if (wid == 0)
        asm volatile("tcgen05.dealloc.cta_group::1.sync.aligned.b32 %0, %1;"
                     :: "r"(tmem), "r"(128u));

#else  // --------- SIMT fp32 fallback ----------
    float* As = (float*)gp;
    const float* Ab = A + (size_t)bm * 192;
    for (int i = tid; i < 128 * 48; i += 256)
        ((float4*)As)[i] = ((const float4*)Ab)[i];
    __syncthreads();
    for (int idx = tid; idx < 128 * Ntot; idx += 256) {
        int col = idx >> 7, row = idx & 127;
        const float4* ar = (const float4*)(As + row * 192);
        const float4* wr = (const float4*)(W + (size_t)col * 192);
        float s = 0.f;
#pragma unroll 8
        for (int k = 0; k < 48; k++) {
            float4 a = ar[k], w = wr[k];
            s += a.x * w.x + a.y * w.y + a.z * w.z + a.w * w.w;
        }
        C[(size_t)(bm + row) * Ntot + col] = s + bias[col];
    }
#endif
}

// ---------------------------------------------------------------------------
// tcgen05 attention: one CTA per (b,w), 512 threads, 6 heads sequential.
// Round-12 structure with the V-buffer overlap FIXED: V region is 5 slabs
// x 4096 = 20480 B (slab 4 half-used for keys 128..143); bias cache moved
// past it. Header shrunk to 1024 B to fit the 227KB smem cap.
// SMEM: hdr 1024 | P 5x18432 @1024 | QK 2x18432 @93184 | V 20480 @130048 |
//       bias cache 6H @150528 (79488) -> end 230016
// ---------------------------------------------------------------------------
#define A_P_OFF   1024u
#define A_QK_OFF  93184u
#define A_V_OFF   130048u
#define A_BC_OFF  150528u
#define ATTN2_SMEM (230016 + 1024)

#if TC_OK
__device__ __forceinline__ int cp6(int c) {   // column part of bias idx, x6
    int jz = c / 72, r = c - jz * 72;
    int jh = r / 12, jw = r - jh * 12;
    return (jz * 1656 + jh * 138 - jw) * 6;
}
#endif

__global__ __launch_bounds__(512, 1) void attn_tc(
    const float* __restrict__ qkv, const float* __restrict__ bias_table,
    const float* __restrict__ mask, float* __restrict__ outp)
{
    extern __shared__ char asm_raw[];
    u32 sb_raw = smem_u32(asm_raw);
    u32 sb0 = (sb_raw + 1023u) & ~1023u;
    char* gp = asm_raw + (sb0 - sb_raw);

    const int tid = threadIdx.x;
    const int w = blockIdx.x >> 1;
    const int b = blockIdx.x & 1;
    const float* gq = qkv + (size_t)(b * NW + w) * NTOK * 576;
    const float* maskb = mask + (size_t)b * NTOK * NTOK;
    float* ga = outp + (size_t)(b * NW + w) * NTOK * DIM;

#if TC_OK
    const int wid = tid >> 5, lane = tid & 31;

    if (wid == 0) {
        asm volatile("tcgen05.alloc.cta_group::1.sync.aligned.shared::cta.b32 [%0], %1;"
                     :: "r"(sb0), "r"(512u) : "memory");
        asm volatile("tcgen05.relinquish_alloc_permit.cta_group::1.sync.aligned;");
    }
    if (tid == 0) mbar_init(sb0 + 16, 1);

    // ---- bias cache for all 6 heads: bc[i*6+h] ----
    {
        float* bc = (float*)(gp + A_BC_OFF);
        for (int idx = tid; idx < TABLE * 6; idx += 512) {
            int i = idx / 6, hh = idx - i * 6;
            bc[idx] = bias_table[(size_t)i * (NW * HEADS) + w * HEADS + hh];
        }
    }

    // roles: warps 0-3 -> D1 queries (all chunks), warp 7 -> D2 tail
    const bool is_smx = (wid < 4) || (wid == 7);
    const bool tail = (wid == 7);
    const int qrow = tail ? 112 + lane : wid * 32 + lane;
    const bool act = (!tail) || (lane >= 16);
    const int dbase = tail ? 144 : 0;
    const u32 lofs = (u32)((tail ? 3 : wid) << 21);
    int rp6 = 0;
    {
        int iz = qrow / 72, rm = qrow - iz * 72;
        int ih = rm / 12, iw = rm - ih * 12;
        rp6 = (iz * 828 + ih * 23 + iw + 11) * 6;
    }
    const float* mrow = maskb + qrow * NTOK;
    __syncthreads();

    u32 tmem;
    asm("ld.shared.b32 %0, [%1];" : "=r"(tmem) : "r"(sb0));
    const float* bcf = (const float*)(gp + A_BC_OFF);
    u32 mph = 0;

    for (int h = 0; h < HEADS; h++) {
        // ---- stage q/k(h) via cp.async (raw: qkv already tf32) ----
        {
            const char* src = (const char*)gq + h * 128;
            for (int idx = tid; idx < 1152; idx += 512) {
                int row = idx >> 3, c4 = idx & 7;
                u32 bo = (u32)(row * 128 + c4 * 16);
                bo ^= (bo >> 3) & 0x70;
                CPA16(sb0 + A_QK_OFF + bo, src + (size_t)row * 2304 + c4 * 16);
                CPA16(sb0 + A_QK_OFF + 18432u + bo,
                      src + (size_t)row * 2304 + 768 + c4 * 16);
            }
            CPA_COMMIT();
        }
        // ---- stage V(h) raw transpose (LDGs overlap the cp.asyncs) ----
        {
            const float* vs = gq + 384 + h * 32;
            for (int idx = tid; idx < 1152; idx += 512) {
                int m = idx % NTOK, d4 = idx / NTOK;
                float4 v = *(const float4*)(vs + (size_t)m * 576 + d4 * 4);
                char* slab = gp + A_V_OFF + (m >> 5) * 4096;
                u32 colb = (u32)((m & 31) * 4);
#pragma unroll
                for (int j = 0; j < 4; j++) {
                    u32 bo = (u32)((d4 * 4 + j) * 128) + colb;
                    bo ^= (bo >> 3) & 0x70;
                    float val = j == 0 ? v.x : (j == 1 ? v.y : (j == 2 ? v.z : v.w));
                    *(u32*)(slab + bo) = __float_as_uint(val);
                }
            }
        }
        CPA_WAIT0();
        asm volatile("fence.proxy.async.shared::cta;" ::: "memory");
        __syncthreads();

        // ---- S MMAs: D1 (q 0..127) @col0, D2 (q 16..143) @col144 ----
        if (tid == 0) {
            ull qd = mk_desc(sb0 + A_QK_OFF);
            ull kd = mk_desc(sb0 + A_QK_OFF + 18432u);
#pragma unroll
            for (int c = 0; c < 4; c++)
                mma_tf32(tmem, qd + c * 2, kd + c * 2, IDESC_S, (u32)(c > 0));
#pragma unroll
            for (int c = 0; c < 4; c++)
                mma_tf32(tmem + 144, qd + 128 + c * 2, kd + c * 2, IDESC_S, (u32)(c > 0));
            asm volatile(
                "tcgen05.commit.cta_group::1.mbarrier::arrive::one.shared::cluster.b64 [%0];"
                :: "r"(sb0 + 16) : "memory");
        }
        mbar_wait(sb0 + 16, mph & 1); mph++;

        // ---- register softmax (full row per thread, QSCALE folded) ----
        float inv = 0.f;
        if (is_smx) {
            TMF_AFTER();
            const float* brp = bcf + rp6 + h;
            const u32 rowb = (u32)(qrow * 128);
            float sum = 0.f;
#pragma unroll
            for (int cc = 0; cc < 5; cc++) {
                u32 dr[32];
                LDTM32(dr, tmem + dbase + cc * 32 + lofs);
                TMWAIT_LD();
                if (act) {
                    char* ps = gp + A_P_OFF + cc * 18432;
#pragma unroll
                    for (int j0 = 0; j0 < 32; j0 += 4) {
                        const int c = cc * 32 + j0;
                        if (c < NTOK) {
                            float4 mv = *(const float4*)(mrow + c);
                            float e0 = __expf(fmaf(__uint_as_float(dr[j0+0]), QSCALE, brp[cp6(c+0)] + mv.x));
                            float e1 = __expf(fmaf(__uint_as_float(dr[j0+1]), QSCALE, brp[cp6(c+1)] + mv.y));
                            float e2 = __expf(fmaf(__uint_as_float(dr[j0+2]), QSCALE, brp[cp6(c+2)] + mv.z));
                            float e3 = __expf(fmaf(__uint_as_float(dr[j0+3]), QSCALE, brp[cp6(c+3)] + mv.w));
                            sum += (e0 + e1) + (e2 + e3);
                            u32 t0 = cvt_tf32(e0), t1 = cvt_tf32(e1);
                            u32 t2 = cvt_tf32(e2), t3 = cvt_tf32(e3);
                            u32 o = rowb + (u32)((c & 31) * 4);
                            o ^= (o >> 3) & 0x70;
                            asm volatile("st.shared.v2.b32 [%0], {%1,%2};"
                                         :: "r"(smem_u32(ps) + o), "r"(t0), "r"(t1));
                            u32 o2 = rowb + (u32)(((c + 2) & 31) * 4);
                            o2 ^= (o2 >> 3) & 0x70;
                            asm volatile("st.shared.v2.b32 [%0], {%1,%2};"
                                         :: "r"(smem_u32(ps) + o2), "r"(t2), "r"(t3));
                        }
                    }
                }
            }
            TMF_BEFORE();
            inv = 1.0f / sum;
        }
        asm volatile("fence.proxy.async.shared::cta;" ::: "memory");
        __syncthreads();

        // ---- PV MMAs (K=144, 18 chunks): O-D1 @288, O-D2 @320 ----
        if (tid == 0) {
            ull pd = mk_desc(sb0 + A_P_OFF);
            ull vd = mk_desc(sb0 + A_V_OFF);
#pragma unroll
            for (int kc = 0; kc < 18; kc++)
                mma_tf32(tmem + 288, pd + (kc >> 2) * 1152 + (kc & 3) * 2,
                                     vd + (kc >> 2) * 256 + (kc & 3) * 2,
                                     IDESC_PV, (u32)(kc > 0));
#pragma unroll
            for (int kc = 0; kc < 18; kc++)
                mma_tf32(tmem + 320, pd + 128 + (kc >> 2) * 1152 + (kc & 3) * 2,
                                     vd + (kc >> 2) * 256 + (kc & 3) * 2,
                                     IDESC_PV, (u32)(kc > 0));
            asm volatile(
                "tcgen05.commit.cta_group::1.mbarrier::arrive::one.shared::cluster.b64 [%0];"
                :: "r"(sb0 + 16) : "memory");
        }
        mbar_wait(sb0 + 16, mph & 1); mph++;

        // ---- O epilogue (inv local; tf32-rounded for a_pre proj GEMM) ----
        if (is_smx) {
            TMF_AFTER();
            u32 dr[32];
            LDTM32(dr, tmem + (tail ? 320u : 288u) + lofs);
            TMWAIT_LD();
            TMF_BEFORE();
            if (act) {
                float* ob = ga + (size_t)qrow * DIM + h * HDIM;
#pragma unroll
                for (int c = 0; c < 8; c++) {
                    float4 o;
                    o.x = __uint_as_float(cvt_tf32(__uint_as_float(dr[4 * c + 0]) * inv));
                    o.y = __uint_as_float(cvt_tf32(__uint_as_float(dr[4 * c + 1]) * inv));
                    o.z = __uint_as_float(cvt_tf32(__uint_as_float(dr[4 * c + 2]) * inv));
                    o.w = __uint_as_float(cvt_tf32(__uint_as_float(dr[4 * c + 3]) * inv));
                    *(float4*)(ob + 4 * c) = o;
                }
            }
        }
        __syncthreads();
    }
    if (wid == 0)
        asm volatile("tcgen05.dealloc.cta_group::1.sync.aligned.b32 %0, %1;"
                     :: "r"(tmem), "r"(512u));

#else  // --------- SIMT fallback ----------
    for (int t = tid; t < HEADS * NTOK; t += 512) {
        int h = t / NTOK, qrow = t - h * NTOK;
        const float* qr = gq + (size_t)qrow * 576 + h * HDIM;
        int iz = qrow / 72, rm = qrow - iz * 72;
        int ih = rm / 12, iw = rm - ih * 12;
        int rp = iz * 828 + ih * 23 + iw + 11;
        float mx = -3.0e38f;
        for (int m = 0; m < NTOK; m++) {
            const float* kr = gq + (size_t)m * 576 + 192 + h * HDIM;
            float s = 0.f;
            for (int d = 0; d < HDIM; d++) s += qr[d] * kr[d];
            int jz = m / 72, rm2 = m - jz * 72;
            int jh = rm2 / 12, jw = rm2 - jh * 12;
            int bi = rp + jz * 1656 + jh * 138 - jw;
            s = s * QSCALE + bias_table[(size_t)bi * (NW * HEADS) + w * HEADS + h]
              + maskb[qrow * NTOK + m];
            mx = fmaxf(mx, s);
        }
        float acc[HDIM];
        for (int d = 0; d < HDIM; d++) acc[d] = 0.f;
        float Z = 0.f;
        for (int m = 0; m < NTOK; m++) {
            const float* kr = gq + (size_t)m * 576 + 192 + h * HDIM;
            float s = 0.f;
            for (int d = 0; d < HDIM; d++) s += qr[d] * kr[d];
            int jz = m / 72, rm2 = m - jz * 72;
            int jh = rm2 / 12, jw = rm2 - jh * 12;
            int bi = rp + jz * 1656 + jh * 138 - jw;
            s = s * QSCALE + bias_table[(size_t)bi * (NW * HEADS) + w * HEADS + h]
              + maskb[qrow * NTOK + m];
            float e = __expf(s - mx);
            Z += e;
            const float* vr = gq + (size_t)m * 576 + 384 + h * HDIM;
            for (int d = 0; d < HDIM; d++) acc[d] += e * vr[d];
        }
        float* ob = ga + (size_t)qrow * DIM + h * HDIM;
        for (int d = 0; d < HDIM; d++) ob[d] = acc[d] / Z;
    }
#endif
}

// ---------------------------------------------------------------------------
extern "C" void kernel_launch(void* const* d_in, const int* in_sizes, int n_in,
                              void* d_out, int out_size)
{
    const float* x    = (const float*)d_in[0];
    const float* mask = (const float*)d_in[1];
    const float* w1   = (const float*)d_in[2];
    const float* b1   = (const float*)d_in[3];
    const float* w2   = (const float*)d_in[4];
    const float* b2   = (const float*)d_in[5];
    const float* bt   = (const float*)d_in[6];
    float* out = (float*)d_out;

    void *qkv_p, *att_p, *wtf_p;
    cudaGetSymbolAddress(&qkv_p, g_qkv);
    cudaGetSymbolAddress(&att_p, g_att);
    cudaGetSymbolAddress(&wtf_p, g_wtf);
    float* qkv = (float*)qkv_p;
    float* att = (float*)att_p;
    float* wtf = (float*)wtf_p;

    cudaFuncSetAttribute(gemm_tc, cudaFuncAttributeMaxDynamicSharedMemorySize, G_SMEM_SZ);
    cudaFuncSetAttribute(attn_tc, cudaFuncAttributeMaxDynamicSharedMemorySize, ATTN2_SMEM);

    // QKV projection: 241920 x 576 x 192 (output tf32-rounded for attn)
    wprep<<<(576 * 48 + 255) / 256, 256>>>(w1, wtf, 576 * 48);
    gemm_tc<<<MTILES, 256, G_SMEM_SZ>>>(x, w1, wtf, b1, qkv, 576, 1, 0);
    // fused attention per (b, w)  (writes tf32-rounded O)
    attn_tc<<<NW * BATCH, 512, ATTN2_SMEM>>>(qkv, bt, mask, att);
    // output projection: 241920 x 192 x 192 (A pre-rounded -> cp.async staging)
    wprep<<<(192 * 48 + 255) / 256, 256>>>(w2, wtf, 192 * 48);
    gemm_tc<<<MTILES, 256, G_SMEM_SZ>>>(att, w2, wtf, b2, out, 192, 0, 1);
}